// round 1
// baseline (speedup 1.0000x reference)
#include <cuda_runtime.h>
#include <math.h>

#define BB   2
#define NN   4096
#define DD   512
#define HH   8
#define HDIM 64
#define CQKV 1536

// Scratch (static device arrays — no runtime allocation)
__device__ float g_qkv[(size_t)BB * NN * CQKV];   // [B,N,3,H,HD] flattened: 50.3 MB
__device__ float g_attn[(size_t)BB * NN * DD];    // [B,N,D]: 16.8 MB

// ---------------------------------------------------------------------------
// Tiled SGEMM with fused bias: C[M,Nc] = A[M,K] @ W[K,Nc] + bias[Nc]
// BM=BN=128, BK=8, 256 threads, 8x8 per-thread micro-tile.
// Assumes M%128==0, Nc%128==0, K%8==0 (true for all our shapes).
// ---------------------------------------------------------------------------
__global__ __launch_bounds__(256) void sgemm_bias_kernel(
    const float* __restrict__ A, const float* __restrict__ W,
    const float* __restrict__ bias, float* __restrict__ C,
    int M, int Nc, int K)
{
    __shared__ float As[8][128];
    __shared__ float Bs[8][128];

    const int tid = threadIdx.x;
    const int tx = tid & 15;
    const int ty = tid >> 4;
    const int row0 = blockIdx.y * 128;
    const int col0 = blockIdx.x * 128;

    const int a_r = tid >> 1;          // 0..127
    const int a_c = (tid & 1) * 4;     // 0 or 4
    const int b_r = tid >> 5;          // 0..7
    const int b_c = (tid & 31) * 4;    // 0..124

    const float* Aptr = A + (size_t)(row0 + a_r) * K + a_c;
    const float* Wptr = W + (size_t)b_r * Nc + col0 + b_c;

    float acc[8][8];
#pragma unroll
    for (int i = 0; i < 8; ++i)
#pragma unroll
        for (int j = 0; j < 8; ++j) acc[i][j] = 0.f;

    for (int k0 = 0; k0 < K; k0 += 8) {
        float4 av = *(const float4*)(Aptr + k0);
        As[a_c + 0][a_r] = av.x;
        As[a_c + 1][a_r] = av.y;
        As[a_c + 2][a_r] = av.z;
        As[a_c + 3][a_r] = av.w;
        *(float4*)&Bs[b_r][b_c] = *(const float4*)(Wptr + (size_t)k0 * Nc);
        __syncthreads();

#pragma unroll
        for (int k = 0; k < 8; ++k) {
            float ra[8], rb[8];
#pragma unroll
            for (int i = 0; i < 8; ++i) ra[i] = As[k][ty * 8 + i];
#pragma unroll
            for (int j = 0; j < 8; ++j) rb[j] = Bs[k][tx * 8 + j];
#pragma unroll
            for (int i = 0; i < 8; ++i)
#pragma unroll
                for (int j = 0; j < 8; ++j)
                    acc[i][j] = fmaf(ra[i], rb[j], acc[i][j]);
        }
        __syncthreads();
    }

#pragma unroll
    for (int i = 0; i < 8; ++i) {
        const int r = row0 + ty * 8 + i;
#pragma unroll
        for (int j = 0; j < 8; j += 4) {
            const int c = col0 + tx * 8 + j;
            float4 o;
            o.x = acc[i][j + 0] + bias[c + 0];
            o.y = acc[i][j + 1] + bias[c + 1];
            o.z = acc[i][j + 2] + bias[c + 2];
            o.w = acc[i][j + 3] + bias[c + 3];
            *(float4*)&C[(size_t)r * Nc + c] = o;
        }
    }
}

// ---------------------------------------------------------------------------
// Flash attention, fp32, causal. One CTA = one (b, h, 64-row q-tile).
// 256 threads (16x16). Thread (ty,tx) owns S rows i=ty*4+r, S cols j=cc*16+tx,
// O cols c=tx*4+cc. Online softmax with running (m, l).
// Dynamic smem: Qs (64x64), KVs (64x68 padded), Ps (64x64) = 50176 B.
// ---------------------------------------------------------------------------
#define STQ 64
#define STK 68
#define STP 64
#define FLASH_SMEM_BYTES ((64 * STQ + 64 * STK + 64 * STP) * 4)

__global__ __launch_bounds__(256) void flash_kernel(
    const float* __restrict__ qkv, float* __restrict__ out)
{
    extern __shared__ float smem[];
    float* Qs  = smem;                     // 64 * 64
    float* KVs = smem + 64 * STQ;          // 64 * 68
    float* Ps  = smem + 64 * STQ + 64 * STK; // 64 * 64

    const int tid = threadIdx.x;
    const int tx = tid & 15;
    const int ty = tid >> 4;
    const int qt = blockIdx.x;
    const int h  = blockIdx.y;
    const int b  = blockIdx.z;
    const float scale = 0.125f;  // 1/sqrt(64)

    // ---- load Q tile (pre-scaled) ----
    {
        const float* qbase = qkv + ((size_t)b * NN + (size_t)qt * 64) * CQKV + h * HDIM;
#pragma unroll
        for (int r = 0; r < 4; ++r) {
            const int idx = tid + 256 * r;
            const int row = idx >> 4;
            const int c4  = (idx & 15) * 4;
            float4 v = *(const float4*)(qbase + (size_t)row * CQKV + c4);
            v.x *= scale; v.y *= scale; v.z *= scale; v.w *= scale;
            *(float4*)&Qs[row * STQ + c4] = v;
        }
    }

    float m[4], l[4], o[4][4];
#pragma unroll
    for (int r = 0; r < 4; ++r) {
        m[r] = -1e30f;
        l[r] = 0.f;
#pragma unroll
        for (int c = 0; c < 4; ++c) o[r][c] = 0.f;
    }

    __syncthreads();

    for (int kt = 0; kt <= qt; ++kt) {
        // ---- load K tile ----
        {
            const float* kbase = qkv + ((size_t)b * NN + (size_t)kt * 64) * CQKV + DD + h * HDIM;
#pragma unroll
            for (int r = 0; r < 4; ++r) {
                const int idx = tid + 256 * r;
                const int row = idx >> 4;
                const int c4  = (idx & 15) * 4;
                *(float4*)&KVs[row * STK + c4] =
                    *(const float4*)(kbase + (size_t)row * CQKV + c4);
            }
        }
        __syncthreads();

        // ---- S = (Q*scale) @ K^T ; s[r][cc] at col j = cc*16+tx ----
        float s[4][4];
#pragma unroll
        for (int r = 0; r < 4; ++r)
#pragma unroll
            for (int c = 0; c < 4; ++c) s[r][c] = 0.f;

#pragma unroll
        for (int d4 = 0; d4 < 16; ++d4) {
            float4 q[4], k[4];
#pragma unroll
            for (int r = 0; r < 4; ++r)
                q[r] = *(const float4*)&Qs[(ty * 4 + r) * STQ + d4 * 4];
#pragma unroll
            for (int c = 0; c < 4; ++c)
                k[c] = *(const float4*)&KVs[(c * 16 + tx) * STK + d4 * 4];
#pragma unroll
            for (int r = 0; r < 4; ++r)
#pragma unroll
                for (int c = 0; c < 4; ++c) {
                    s[r][c] = fmaf(q[r].x, k[c].x, s[r][c]);
                    s[r][c] = fmaf(q[r].y, k[c].y, s[r][c]);
                    s[r][c] = fmaf(q[r].z, k[c].z, s[r][c]);
                    s[r][c] = fmaf(q[r].w, k[c].w, s[r][c]);
                }
        }

        // ---- causal mask on diagonal tile ----
        if (kt == qt) {
#pragma unroll
            for (int r = 0; r < 4; ++r)
#pragma unroll
                for (int c = 0; c < 4; ++c)
                    if (c * 16 + tx > ty * 4 + r) s[r][c] = -1e30f;
        }

        // ---- online softmax update ----
#pragma unroll
        for (int r = 0; r < 4; ++r) {
            float mx = fmaxf(fmaxf(s[r][0], s[r][1]), fmaxf(s[r][2], s[r][3]));
#pragma unroll
            for (int off = 8; off; off >>= 1)
                mx = fmaxf(mx, __shfl_xor_sync(0xffffffffu, mx, off, 16));
            const float mnew = fmaxf(m[r], mx);
            float sum = 0.f;
#pragma unroll
            for (int c = 0; c < 4; ++c) {
                const float p = __expf(s[r][c] - mnew);
                s[r][c] = p;
                sum += p;
            }
#pragma unroll
            for (int off = 8; off; off >>= 1)
                sum += __shfl_xor_sync(0xffffffffu, sum, off, 16);
            const float alpha = __expf(m[r] - mnew);
            m[r] = mnew;
            l[r] = l[r] * alpha + sum;
#pragma unroll
            for (int c = 0; c < 4; ++c) o[r][c] *= alpha;
        }

        __syncthreads();  // everyone done reading K from KVs

        // ---- store P, load V into KVs ----
#pragma unroll
        for (int r = 0; r < 4; ++r)
#pragma unroll
            for (int c = 0; c < 4; ++c)
                Ps[(ty * 4 + r) * STP + c * 16 + tx] = s[r][c];
        {
            const float* vbase = qkv + ((size_t)b * NN + (size_t)kt * 64) * CQKV + 2 * DD + h * HDIM;
#pragma unroll
            for (int r = 0; r < 4; ++r) {
                const int idx = tid + 256 * r;
                const int row = idx >> 4;
                const int c4  = (idx & 15) * 4;
                *(float4*)&KVs[row * STK + c4] =
                    *(const float4*)(vbase + (size_t)row * CQKV + c4);
            }
        }
        __syncthreads();

        // ---- O += P @ V ; o[r][cc] at out col c = tx*4+cc ----
#pragma unroll
        for (int j4 = 0; j4 < 16; ++j4) {
            float4 p[4];
#pragma unroll
            for (int r = 0; r < 4; ++r)
                p[r] = *(const float4*)&Ps[(ty * 4 + r) * STP + j4 * 4];
            float4 v[4];
#pragma unroll
            for (int jj = 0; jj < 4; ++jj)
                v[jj] = *(const float4*)&KVs[(j4 * 4 + jj) * STK + tx * 4];
#pragma unroll
            for (int r = 0; r < 4; ++r) {
                o[r][0] = fmaf(p[r].x, v[0].x, o[r][0]);
                o[r][1] = fmaf(p[r].x, v[0].y, o[r][1]);
                o[r][2] = fmaf(p[r].x, v[0].z, o[r][2]);
                o[r][3] = fmaf(p[r].x, v[0].w, o[r][3]);
                o[r][0] = fmaf(p[r].y, v[1].x, o[r][0]);
                o[r][1] = fmaf(p[r].y, v[1].y, o[r][1]);
                o[r][2] = fmaf(p[r].y, v[1].z, o[r][2]);
                o[r][3] = fmaf(p[r].y, v[1].w, o[r][3]);
                o[r][0] = fmaf(p[r].z, v[2].x, o[r][0]);
                o[r][1] = fmaf(p[r].z, v[2].y, o[r][1]);
                o[r][2] = fmaf(p[r].z, v[2].z, o[r][2]);
                o[r][3] = fmaf(p[r].z, v[2].w, o[r][3]);
                o[r][0] = fmaf(p[r].w, v[3].x, o[r][0]);
                o[r][1] = fmaf(p[r].w, v[3].y, o[r][1]);
                o[r][2] = fmaf(p[r].w, v[3].z, o[r][2]);
                o[r][3] = fmaf(p[r].w, v[3].w, o[r][3]);
            }
        }
        __syncthreads();  // protect KVs/Ps before next iteration's loads
    }

    // ---- epilogue: normalize and write [B,N,H,HD] layout (== [B,N,D]) ----
    {
        float* obase = out + ((size_t)b * NN + (size_t)qt * 64) * DD + h * HDIM;
#pragma unroll
        for (int r = 0; r < 4; ++r) {
            const float inv = 1.f / l[r];
            const int row = ty * 4 + r;
            float4 res;
            res.x = o[r][0] * inv;
            res.y = o[r][1] * inv;
            res.z = o[r][2] * inv;
            res.w = o[r][3] * inv;
            *(float4*)(obase + (size_t)row * DD + tx * 4) = res;
        }
    }
}

// ---------------------------------------------------------------------------
extern "C" void kernel_launch(void* const* d_in, const int* in_sizes, int n_in,
                              void* d_out, int out_size)
{
    (void)in_sizes; (void)n_in; (void)out_size;
    const float* x    = (const float*)d_in[0];
    const float* Wqkv = (const float*)d_in[1];
    const float* bqkv = (const float*)d_in[2];
    const float* Wout = (const float*)d_in[3];
    const float* bout = (const float*)d_in[4];
    float* out = (float*)d_out;

    float *qkv, *attn;
    cudaGetSymbolAddress((void**)&qkv, g_qkv);
    cudaGetSymbolAddress((void**)&attn, g_attn);

    // 1) QKV projection: [8192,512] @ [512,1536] + bias
    {
        dim3 grid(CQKV / 128, (BB * NN) / 128);
        sgemm_bias_kernel<<<grid, 256>>>(x, Wqkv, bqkv, qkv, BB * NN, CQKV, DD);
    }

    // 2) causal flash attention
    {
        cudaFuncSetAttribute(flash_kernel,
                             cudaFuncAttributeMaxDynamicSharedMemorySize,
                             FLASH_SMEM_BYTES);
        dim3 grid(NN / 64, HH, BB);
        flash_kernel<<<grid, 256, FLASH_SMEM_BYTES>>>(qkv, attn);
    }

    // 3) output projection: [8192,512] @ [512,512] + bias
    {
        dim3 grid(DD / 128, (BB * NN) / 128);
        sgemm_bias_kernel<<<grid, 256>>>(attn, Wout, bout, out, BB * NN, DD, DD);
    }
}

// round 2
// speedup vs baseline: 3.0147x; 3.0147x over previous
#include <cuda_runtime.h>
#include <stdint.h>

#define BB   2
#define NN   4096
#define DD   512
#define HH   8
#define HDIM 64
#define CQKV 1536

// Scratch (static device arrays — no runtime allocation)
__device__ float g_qkv[(size_t)BB * NN * CQKV];   // [B,N,3,H,HD]
__device__ float g_attn[(size_t)BB * NN * DD];    // [B,N,D]

// ---------------------------------------------------------------------------
// helpers
// ---------------------------------------------------------------------------
__device__ __forceinline__ uint32_t f2tf(float x) {
    uint32_t u;
    asm("cvt.rna.tf32.f32 %0, %1;" : "=r"(u) : "f"(x));
    return u;
}

__device__ __forceinline__ void mma8(float* c,
    uint32_t a0, uint32_t a1, uint32_t a2, uint32_t a3,
    uint32_t b0, uint32_t b1)
{
    asm volatile(
        "mma.sync.aligned.m16n8k8.row.col.f32.tf32.tf32.f32 "
        "{%0,%1,%2,%3}, {%4,%5,%6,%7}, {%8,%9}, {%0,%1,%2,%3};"
        : "+f"(c[0]), "+f"(c[1]), "+f"(c[2]), "+f"(c[3])
        : "r"(a0), "r"(a1), "r"(a2), "r"(a3), "r"(b0), "r"(b1));
}

// ---------------------------------------------------------------------------
// TF32 GEMM with fused bias: C[M,Nc] = A[M,K] @ W[K,Nc] + bias
// BM=128, BN=128, BK=32, 256 threads (8 warps, 2x4), warp tile 64x32.
// Requires M%128==0, Nc%128==0, K%32==0.
// ---------------------------------------------------------------------------
#define STRA 36    // 128 x 36 smem A, bank-free frag loads (stride ≡ 4 mod 32)
#define STRB 136   // 32 x 136 smem B, bank-free frag loads (stride ≡ 8 mod 32)

__global__ __launch_bounds__(256) void gemm_tf32(
    const float* __restrict__ A, const float* __restrict__ W,
    const float* __restrict__ bias, float* __restrict__ C,
    int M, int Nc, int K)
{
    __shared__ uint32_t As[128 * STRA];
    __shared__ uint32_t Bs[32 * STRB];

    const int tid  = threadIdx.x;
    const int lane = tid & 31;
    const int warp = tid >> 5;
    const int wm = warp >> 2;      // 0..1
    const int wn = warp & 3;       // 0..3
    const int r0 = lane >> 2;      // 0..7
    const int q  = lane & 3;       // 0..3
    const int row0 = blockIdx.y * 128;
    const int col0 = blockIdx.x * 128;

    const int ar = tid >> 3;           // 0..31
    const int ac = (tid & 7) * 4;      // 0..28
    const int br = tid >> 5;           // 0..7
    const int bc = (tid & 31) * 4;     // 0..124

    const float* Ag = A + (size_t)(row0 + ar) * K + ac;
    const float* Wg = W + (size_t)br * Nc + col0 + bc;

    float acc[4][4][4];
#pragma unroll
    for (int i = 0; i < 4; ++i)
#pragma unroll
        for (int j = 0; j < 4; ++j)
#pragma unroll
            for (int v = 0; v < 4; ++v) acc[i][j][v] = 0.f;

    for (int k0 = 0; k0 < K; k0 += 32) {
        // global -> smem (with tf32 rounding)
#pragma unroll
        for (int i = 0; i < 4; ++i) {
            float4 v = *(const float4*)(Ag + (size_t)(i * 32) * K + k0);
            const int rr = ar + i * 32;
            As[rr * STRA + ac + 0] = f2tf(v.x);
            As[rr * STRA + ac + 1] = f2tf(v.y);
            As[rr * STRA + ac + 2] = f2tf(v.z);
            As[rr * STRA + ac + 3] = f2tf(v.w);
        }
#pragma unroll
        for (int i = 0; i < 4; ++i) {
            float4 v = *(const float4*)(Wg + (size_t)(k0 + i * 8) * Nc);
            const int rr = br + i * 8;
            Bs[rr * STRB + bc + 0] = f2tf(v.x);
            Bs[rr * STRB + bc + 1] = f2tf(v.y);
            Bs[rr * STRB + bc + 2] = f2tf(v.z);
            Bs[rr * STRB + bc + 3] = f2tf(v.w);
        }
        __syncthreads();

#pragma unroll
        for (int kk = 0; kk < 4; ++kk) {
            const int kb = kk * 8;
            uint32_t a[4][4], b[4][2];
#pragma unroll
            for (int mt = 0; mt < 4; ++mt) {
                const int base = (wm * 64 + mt * 16 + r0) * STRA + kb + q;
                a[mt][0] = As[base];
                a[mt][1] = As[base + 8 * STRA];
                a[mt][2] = As[base + 4];
                a[mt][3] = As[base + 8 * STRA + 4];
            }
#pragma unroll
            for (int nt = 0; nt < 4; ++nt) {
                const int nb = wn * 32 + nt * 8 + r0;
                b[nt][0] = Bs[(kb + q) * STRB + nb];
                b[nt][1] = Bs[(kb + 4 + q) * STRB + nb];
            }
#pragma unroll
            for (int mt = 0; mt < 4; ++mt)
#pragma unroll
                for (int nt = 0; nt < 4; ++nt)
                    mma8(acc[mt][nt], a[mt][0], a[mt][1], a[mt][2], a[mt][3],
                         b[nt][0], b[nt][1]);
        }
        __syncthreads();
    }

    // epilogue: bias + store
#pragma unroll
    for (int mt = 0; mt < 4; ++mt) {
        const int r = row0 + wm * 64 + mt * 16 + r0;
#pragma unroll
        for (int nt = 0; nt < 4; ++nt) {
            const int c = col0 + wn * 32 + nt * 8 + 2 * q;
            const float bx = bias[c], by = bias[c + 1];
            float2 v0 = { acc[mt][nt][0] + bx, acc[mt][nt][1] + by };
            float2 v1 = { acc[mt][nt][2] + bx, acc[mt][nt][3] + by };
            *(float2*)&C[(size_t)r * Nc + c] = v0;
            *(float2*)&C[(size_t)(r + 8) * Nc + c] = v1;
        }
    }
}

// ---------------------------------------------------------------------------
// Flash attention, TF32 tensor-core, causal. One CTA = (b, h, 64-row q-tile).
// 128 threads (4 warps); each warp owns 16 q-rows. P->A-fragment conversion
// via intra-quad shuffles (no smem, no barrier).
// Dynamic smem: Qs 64x68, Ks 64x68, Vs 64x72 (uint32/tf32) = 53248 B.
// ---------------------------------------------------------------------------
#define SQ 68
#define SK 68
#define SV 72
#define FLASH_SMEM ((64 * SQ + 64 * SK + 64 * SV) * 4)

__global__ __launch_bounds__(128) void flash_tf32(
    const float* __restrict__ qkv, float* __restrict__ out)
{
    extern __shared__ uint32_t fsm[];
    uint32_t* Qs = fsm;
    uint32_t* Ks = fsm + 64 * SQ;
    uint32_t* Vs = fsm + 64 * SQ + 64 * SK;

    const int tid  = threadIdx.x;
    const int lane = tid & 31;
    const int warp = tid >> 5;
    const int r0 = lane >> 2;
    const int q  = lane & 3;
    const int qt = blockIdx.x;
    const int h  = blockIdx.y;
    const int b  = blockIdx.z;
    const float scale = 0.125f;   // 1/sqrt(64)

    const int lrow = tid >> 4;          // 0..7
    const int lcol = (tid & 15) * 4;    // 0..60

    // ---- load Q tile (scaled, tf32-rounded) ----
    {
        const float* qb = qkv + ((size_t)b * NN + (size_t)qt * 64) * CQKV + h * HDIM;
#pragma unroll
        for (int i = 0; i < 8; ++i) {
            const int row = lrow + i * 8;
            float4 v = *(const float4*)(qb + (size_t)row * CQKV + lcol);
            Qs[row * SQ + lcol + 0] = f2tf(v.x * scale);
            Qs[row * SQ + lcol + 1] = f2tf(v.y * scale);
            Qs[row * SQ + lcol + 2] = f2tf(v.z * scale);
            Qs[row * SQ + lcol + 3] = f2tf(v.w * scale);
        }
    }
    __syncthreads();

    // ---- preload Q A-fragments (reused for every kt) ----
    uint32_t qa[8][4];
    {
        const int mrow = warp * 16 + r0;
#pragma unroll
        for (int j = 0; j < 8; ++j) {
            const int base = mrow * SQ + j * 8 + q;
            qa[j][0] = Qs[base];
            qa[j][1] = Qs[base + 8 * SQ];
            qa[j][2] = Qs[base + 4];
            qa[j][3] = Qs[base + 8 * SQ + 4];
        }
    }

    float o[8][4];
#pragma unroll
    for (int t = 0; t < 8; ++t)
#pragma unroll
        for (int v = 0; v < 4; ++v) o[t][v] = 0.f;
    float m0 = -1e30f, m1 = -1e30f, l0 = 0.f, l1 = 0.f;

    const float* kb = qkv + (size_t)b * NN * CQKV + DD + h * HDIM;
    const float* vb = qkv + (size_t)b * NN * CQKV + 2 * DD + h * HDIM;

    for (int kt = 0; kt <= qt; ++kt) {
        // ---- load K and V tiles ----
        {
            const float* kbt = kb + (size_t)(kt * 64) * CQKV;
            const float* vbt = vb + (size_t)(kt * 64) * CQKV;
#pragma unroll
            for (int i = 0; i < 8; ++i) {
                const int row = lrow + i * 8;
                float4 kv = *(const float4*)(kbt + (size_t)row * CQKV + lcol);
                Ks[row * SK + lcol + 0] = f2tf(kv.x);
                Ks[row * SK + lcol + 1] = f2tf(kv.y);
                Ks[row * SK + lcol + 2] = f2tf(kv.z);
                Ks[row * SK + lcol + 3] = f2tf(kv.w);
                float4 vv = *(const float4*)(vbt + (size_t)row * CQKV + lcol);
                Vs[row * SV + lcol + 0] = f2tf(vv.x);
                Vs[row * SV + lcol + 1] = f2tf(vv.y);
                Vs[row * SV + lcol + 2] = f2tf(vv.z);
                Vs[row * SV + lcol + 3] = f2tf(vv.w);
            }
        }
        __syncthreads();

        // ---- S = Q @ K^T (m16 x n64, k=64) ----
        float s[8][4];
#pragma unroll
        for (int nt = 0; nt < 8; ++nt)
#pragma unroll
            for (int v = 0; v < 4; ++v) s[nt][v] = 0.f;

#pragma unroll
        for (int j = 0; j < 8; ++j) {
#pragma unroll
            for (int nt = 0; nt < 8; ++nt) {
                const int base = (nt * 8 + r0) * SK + j * 8 + q;
                const uint32_t b0 = Ks[base];
                const uint32_t b1 = Ks[base + 4];
                mma8(s[nt], qa[j][0], qa[j][1], qa[j][2], qa[j][3], b0, b1);
            }
        }

        // ---- causal mask (diagonal tile only) ----
        if (kt == qt) {
            const int rg = warp * 16 + r0;
#pragma unroll
            for (int nt = 0; nt < 8; ++nt) {
                const int c = nt * 8 + 2 * q;
                if (c     > rg)     s[nt][0] = -1e30f;
                if (c + 1 > rg)     s[nt][1] = -1e30f;
                if (c     > rg + 8) s[nt][2] = -1e30f;
                if (c + 1 > rg + 8) s[nt][3] = -1e30f;
            }
        }

        // ---- online softmax ----
        float mx0 = -1e30f, mx1 = -1e30f;
#pragma unroll
        for (int nt = 0; nt < 8; ++nt) {
            mx0 = fmaxf(mx0, fmaxf(s[nt][0], s[nt][1]));
            mx1 = fmaxf(mx1, fmaxf(s[nt][2], s[nt][3]));
        }
        mx0 = fmaxf(mx0, __shfl_xor_sync(0xffffffffu, mx0, 1));
        mx0 = fmaxf(mx0, __shfl_xor_sync(0xffffffffu, mx0, 2));
        mx1 = fmaxf(mx1, __shfl_xor_sync(0xffffffffu, mx1, 1));
        mx1 = fmaxf(mx1, __shfl_xor_sync(0xffffffffu, mx1, 2));

        const float mn0 = fmaxf(m0, mx0);
        const float mn1 = fmaxf(m1, mx1);
        float sum0 = 0.f, sum1 = 0.f;
#pragma unroll
        for (int nt = 0; nt < 8; ++nt) {
            s[nt][0] = __expf(s[nt][0] - mn0);
            s[nt][1] = __expf(s[nt][1] - mn0);
            s[nt][2] = __expf(s[nt][2] - mn1);
            s[nt][3] = __expf(s[nt][3] - mn1);
            sum0 += s[nt][0] + s[nt][1];
            sum1 += s[nt][2] + s[nt][3];
        }
        sum0 += __shfl_xor_sync(0xffffffffu, sum0, 1);
        sum0 += __shfl_xor_sync(0xffffffffu, sum0, 2);
        sum1 += __shfl_xor_sync(0xffffffffu, sum1, 1);
        sum1 += __shfl_xor_sync(0xffffffffu, sum1, 2);

        const float al0 = __expf(m0 - mn0);
        const float al1 = __expf(m1 - mn1);
        m0 = mn0; m1 = mn1;
        l0 = l0 * al0 + sum0;
        l1 = l1 * al1 + sum1;
#pragma unroll
        for (int t = 0; t < 8; ++t) {
            o[t][0] *= al0; o[t][1] *= al0;
            o[t][2] *= al1; o[t][3] *= al1;
        }

        // ---- O += P @ V ; P fragments built via intra-quad shuffles ----
        const int src_lo = (lane & ~3) | (q >> 1);
        const int src_hi = src_lo + 2;
#pragma unroll
        for (int j = 0; j < 8; ++j) {
            const uint32_t p0 = f2tf(s[j][0]);
            const uint32_t p1 = f2tf(s[j][1]);
            const uint32_t p2 = f2tf(s[j][2]);
            const uint32_t p3 = f2tf(s[j][3]);
            const uint32_t t00 = __shfl_sync(0xffffffffu, p0, src_lo);
            const uint32_t t01 = __shfl_sync(0xffffffffu, p1, src_lo);
            const uint32_t t20 = __shfl_sync(0xffffffffu, p2, src_lo);
            const uint32_t t21 = __shfl_sync(0xffffffffu, p3, src_lo);
            const uint32_t t40 = __shfl_sync(0xffffffffu, p0, src_hi);
            const uint32_t t41 = __shfl_sync(0xffffffffu, p1, src_hi);
            const uint32_t t60 = __shfl_sync(0xffffffffu, p2, src_hi);
            const uint32_t t61 = __shfl_sync(0xffffffffu, p3, src_hi);
            const uint32_t a0 = (q & 1) ? t01 : t00;
            const uint32_t a1 = (q & 1) ? t21 : t20;
            const uint32_t a2 = (q & 1) ? t41 : t40;
            const uint32_t a3 = (q & 1) ? t61 : t60;
#pragma unroll
            for (int dt = 0; dt < 8; ++dt) {
                const uint32_t b0 = Vs[(j * 8 + q) * SV + dt * 8 + r0];
                const uint32_t b1 = Vs[(j * 8 + 4 + q) * SV + dt * 8 + r0];
                mma8(o[dt], a0, a1, a2, a3, b0, b1);
            }
        }
        __syncthreads();   // protect Ks/Vs before next tile's loads
    }

    // ---- epilogue: normalize, write [B,N,H,HD] ----
    {
        const float il0 = 1.f / l0;
        const float il1 = 1.f / l1;
        float* ob = out + ((size_t)b * NN + (size_t)qt * 64 + warp * 16 + r0) * DD + h * HDIM;
#pragma unroll
        for (int dt = 0; dt < 8; ++dt) {
            float2 v0 = { o[dt][0] * il0, o[dt][1] * il0 };
            float2 v1 = { o[dt][2] * il1, o[dt][3] * il1 };
            *(float2*)(ob + dt * 8 + 2 * q) = v0;
            *(float2*)(ob + (size_t)8 * DD + dt * 8 + 2 * q) = v1;
        }
    }
}

// ---------------------------------------------------------------------------
extern "C" void kernel_launch(void* const* d_in, const int* in_sizes, int n_in,
                              void* d_out, int out_size)
{
    (void)in_sizes; (void)n_in; (void)out_size;
    const float* x    = (const float*)d_in[0];
    const float* Wqkv = (const float*)d_in[1];
    const float* bqkv = (const float*)d_in[2];
    const float* Wout = (const float*)d_in[3];
    const float* bout = (const float*)d_in[4];
    float* out = (float*)d_out;

    float *qkv, *attn;
    cudaGetSymbolAddress((void**)&qkv, g_qkv);
    cudaGetSymbolAddress((void**)&attn, g_attn);

    // 1) QKV projection: [8192,512] @ [512,1536] + bias
    {
        dim3 grid(CQKV / 128, (BB * NN) / 128);
        gemm_tf32<<<grid, 256>>>(x, Wqkv, bqkv, qkv, BB * NN, CQKV, DD);
    }

    // 2) causal flash attention (TF32 tensor cores)
    {
        static int set_attr = 0;
        if (!set_attr) {
            cudaFuncSetAttribute(flash_tf32,
                                 cudaFuncAttributeMaxDynamicSharedMemorySize,
                                 FLASH_SMEM);
            set_attr = 1;
        }
        dim3 grid(NN / 64, HH, BB);
        flash_tf32<<<grid, 128, FLASH_SMEM>>>(qkv, attn);
    }

    // 3) output projection: [8192,512] @ [512,512] + bias
    {
        dim3 grid(DD / 128, (BB * NN) / 128);
        gemm_tf32<<<grid, 256>>>(attn, Wout, bout, out, BB * NN, DD, DD);
    }
}

// round 3
// speedup vs baseline: 3.6547x; 1.2123x over previous
#include <cuda_runtime.h>
#include <stdint.h>

#define BB   2
#define NN   4096
#define DD   512
#define HH   8
#define HDIM 64
#define CQKV 1536

// Scratch (static device arrays — no runtime allocation)
__device__ float g_qkv[(size_t)BB * NN * CQKV];   // [B,N,3,H,HD]
__device__ float g_attn[(size_t)BB * NN * DD];    // [B,N,D]

// ---------------------------------------------------------------------------
// helpers
// ---------------------------------------------------------------------------
__device__ __forceinline__ uint32_t f2tf(float x) {
    uint32_t u;
    asm("cvt.rna.tf32.f32 %0, %1;" : "=r"(u) : "f"(x));
    return u;
}

__device__ __forceinline__ void mma8(float* c,
    uint32_t a0, uint32_t a1, uint32_t a2, uint32_t a3,
    uint32_t b0, uint32_t b1)
{
    asm volatile(
        "mma.sync.aligned.m16n8k8.row.col.f32.tf32.tf32.f32 "
        "{%0,%1,%2,%3}, {%4,%5,%6,%7}, {%8,%9}, {%0,%1,%2,%3};"
        : "+f"(c[0]), "+f"(c[1]), "+f"(c[2]), "+f"(c[3])
        : "r"(a0), "r"(a1), "r"(a2), "r"(a3), "r"(b0), "r"(b1));
}

// ---------------------------------------------------------------------------
// TF32 GEMM, fused bias, double-buffered smem + register prefetch.
// BM=128, BN=128, BK=32, 256 threads (8 warps 2x4), warp tile 64x32.
// dynamic smem: 2 x (128*36 + 32*136) words = 71680 B
// ---------------------------------------------------------------------------
#define STRA 36
#define STRB 136
#define GEMM_SMEM ((128 * STRA + 32 * STRB) * 2 * 4)

__global__ __launch_bounds__(256, 2) void gemm_tf32(
    const float* __restrict__ A, const float* __restrict__ W,
    const float* __restrict__ bias, float* __restrict__ C,
    int M, int Nc, int K)
{
    extern __shared__ uint32_t gsm[];
    // layout: As0 @0 (4608), Bs0 @4608 (4352), As1 @8960, Bs1 @13312

    const int tid  = threadIdx.x;
    const int lane = tid & 31;
    const int warp = tid >> 5;
    const int wm = warp >> 2;
    const int wn = warp & 3;
    const int r0 = lane >> 2;
    const int q  = lane & 3;
    const int row0 = blockIdx.y * 128;
    const int col0 = blockIdx.x * 128;

    const int ar = tid >> 3;           // 0..31
    const int ac = (tid & 7) * 4;      // 0..28
    const int br = tid >> 5;           // 0..7
    const int bc = (tid & 31) * 4;     // 0..124

    const float* Ag = A + (size_t)(row0 + ar) * K + ac;
    const float* Wg = W + (size_t)br * Nc + col0 + bc;

    float acc[4][4][4];
#pragma unroll
    for (int i = 0; i < 4; ++i)
#pragma unroll
        for (int j = 0; j < 4; ++j)
#pragma unroll
            for (int v = 0; v < 4; ++v) acc[i][j][v] = 0.f;

    float4 a_st[4], b_st[4];
#pragma unroll
    for (int i = 0; i < 4; ++i)
        a_st[i] = *(const float4*)(Ag + (size_t)(i * 32) * K);
#pragma unroll
    for (int i = 0; i < 4; ++i)
        b_st[i] = *(const float4*)(Wg + (size_t)(i * 8) * Nc);

    // stage buffer 0
    {
        uint32_t* As = gsm;
        uint32_t* Bs = gsm + 4608;
#pragma unroll
        for (int i = 0; i < 4; ++i) {
            uint4 t = { f2tf(a_st[i].x), f2tf(a_st[i].y), f2tf(a_st[i].z), f2tf(a_st[i].w) };
            *(uint4*)&As[(ar + i * 32) * STRA + ac] = t;
        }
#pragma unroll
        for (int i = 0; i < 4; ++i) {
            uint4 t = { f2tf(b_st[i].x), f2tf(b_st[i].y), f2tf(b_st[i].z), f2tf(b_st[i].w) };
            *(uint4*)&Bs[(br + i * 8) * STRB + bc] = t;
        }
    }
    __syncthreads();

    const int nk = K >> 5;
    for (int it = 0; it < nk; ++it) {
        const uint32_t* As = gsm + (it & 1) * 8960;
        const uint32_t* Bs = gsm + 4608 + (it & 1) * 8960;

        // prefetch next K-slab into registers (overlaps with mma below)
        if (it + 1 < nk) {
            const int k0 = (it + 1) * 32;
#pragma unroll
            for (int i = 0; i < 4; ++i)
                a_st[i] = *(const float4*)(Ag + (size_t)(i * 32) * K + k0);
#pragma unroll
            for (int i = 0; i < 4; ++i)
                b_st[i] = *(const float4*)(Wg + (size_t)(k0 + i * 8) * Nc);
        }

#pragma unroll
        for (int kk = 0; kk < 4; ++kk) {
            const int kb = kk * 8;
            uint32_t a[4][4], b[4][2];
#pragma unroll
            for (int mt = 0; mt < 4; ++mt) {
                const int base = (wm * 64 + mt * 16 + r0) * STRA + kb + q;
                a[mt][0] = As[base];
                a[mt][1] = As[base + 8 * STRA];
                a[mt][2] = As[base + 4];
                a[mt][3] = As[base + 8 * STRA + 4];
            }
#pragma unroll
            for (int nt = 0; nt < 4; ++nt) {
                const int nb = wn * 32 + nt * 8 + r0;
                b[nt][0] = Bs[(kb + q) * STRB + nb];
                b[nt][1] = Bs[(kb + 4 + q) * STRB + nb];
            }
#pragma unroll
            for (int mt = 0; mt < 4; ++mt)
#pragma unroll
                for (int nt = 0; nt < 4; ++nt)
                    mma8(acc[mt][nt], a[mt][0], a[mt][1], a[mt][2], a[mt][3],
                         b[nt][0], b[nt][1]);
        }

        // stage next buffer
        if (it + 1 < nk) {
            uint32_t* Asn = gsm + ((it + 1) & 1) * 8960;
            uint32_t* Bsn = gsm + 4608 + ((it + 1) & 1) * 8960;
#pragma unroll
            for (int i = 0; i < 4; ++i) {
                uint4 t = { f2tf(a_st[i].x), f2tf(a_st[i].y), f2tf(a_st[i].z), f2tf(a_st[i].w) };
                *(uint4*)&Asn[(ar + i * 32) * STRA + ac] = t;
            }
#pragma unroll
            for (int i = 0; i < 4; ++i) {
                uint4 t = { f2tf(b_st[i].x), f2tf(b_st[i].y), f2tf(b_st[i].z), f2tf(b_st[i].w) };
                *(uint4*)&Bsn[(br + i * 8) * STRB + bc] = t;
            }
        }
        __syncthreads();
    }

    // epilogue
#pragma unroll
    for (int mt = 0; mt < 4; ++mt) {
        const int r = row0 + wm * 64 + mt * 16 + r0;
#pragma unroll
        for (int nt = 0; nt < 4; ++nt) {
            const int c = col0 + wn * 32 + nt * 8 + 2 * q;
            const float bx = bias[c], by = bias[c + 1];
            float2 v0 = { acc[mt][nt][0] + bx, acc[mt][nt][1] + by };
            float2 v1 = { acc[mt][nt][2] + bx, acc[mt][nt][3] + by };
            *(float2*)&C[(size_t)r * Nc + c] = v0;
            *(float2*)&C[(size_t)(r + 8) * Nc + c] = v1;
        }
    }
}

// ---------------------------------------------------------------------------
// Flash attention v2: BM=128 (8 warps), BN=64, double-buffered K/V smem with
// register-staged prefetch, ONE sync per kt tile. Q smem aliased over buf1.
// smem words: K0 @0 (64*68), V0 @4352 (64*72), K1 @8960, V1 @13312; Qs @8960.
// total 17920 words = 71680 B.
// ---------------------------------------------------------------------------
#define SK 68
#define SV 72
#define SQ 68
#define FLASH_SMEM (17920 * 4)

__global__ __launch_bounds__(256) void flash_tf32(
    const float* __restrict__ qkv, float* __restrict__ out)
{
    extern __shared__ uint32_t fsm[];
    uint32_t* Qs = fsm + 8960;     // alias over K1/V1

    const int tid  = threadIdx.x;
    const int lane = tid & 31;
    const int warp = tid >> 5;     // 0..7
    const int r0 = lane >> 2;
    const int q  = lane & 3;

    // descending-qt schedule: heavy CTAs first
    const int idx = blockIdx.x;            // 0..511
    const int qt  = 31 - (idx >> 4);
    const int h   = idx & 7;
    const int b   = (idx >> 3) & 1;
    const float scale = 0.125f;

    // K/V staging geometry (64x64 tile, 4 float4 per thread)
    const int srow = tid >> 4;            // 0..15
    const int scol = (tid & 15) * 4;      // 0..60

    const float* kb = qkv + (size_t)b * NN * CQKV + DD + h * HDIM;
    const float* vb = qkv + (size_t)b * NN * CQKV + 2 * DD + h * HDIM;

    // ---- load Q tile (128x64) into alias region, and stage K0/V0 ----
    {
        const float* qb = qkv + ((size_t)b * NN + (size_t)qt * 128) * CQKV + h * HDIM;
#pragma unroll
        for (int i = 0; i < 8; ++i) {
            const int row = (tid >> 4) + i * 16;
            float4 v = *(const float4*)(qb + (size_t)row * CQKV + scol);
            uint4 t = { f2tf(v.x * scale), f2tf(v.y * scale),
                        f2tf(v.z * scale), f2tf(v.w * scale) };
            *(uint4*)&Qs[row * SQ + scol] = t;
        }
    }
    {
#pragma unroll
        for (int i = 0; i < 4; ++i) {
            const int row = srow + i * 16;
            float4 kv = *(const float4*)(kb + (size_t)row * CQKV + scol);
            uint4 t = { f2tf(kv.x), f2tf(kv.y), f2tf(kv.z), f2tf(kv.w) };
            *(uint4*)&fsm[row * SK + scol] = t;
            float4 vv = *(const float4*)(vb + (size_t)row * CQKV + scol);
            uint4 u = { f2tf(vv.x), f2tf(vv.y), f2tf(vv.z), f2tf(vv.w) };
            *(uint4*)&fsm[4352 + row * SV + scol] = u;
        }
    }
    __syncthreads();

    // ---- preload Q A-fragments ----
    uint32_t qa[8][4];
    {
        const int mrow = warp * 16 + r0;
#pragma unroll
        for (int j = 0; j < 8; ++j) {
            const int base = mrow * SQ + j * 8 + q;
            qa[j][0] = Qs[base];
            qa[j][1] = Qs[base + 8 * SQ];
            qa[j][2] = Qs[base + 4];
            qa[j][3] = Qs[base + 8 * SQ + 4];
        }
    }
    __syncthreads();   // alias region free for buffer-1 writes after this

    float o[8][4];
#pragma unroll
    for (int t = 0; t < 8; ++t)
#pragma unroll
        for (int v = 0; v < 4; ++v) o[t][v] = 0.f;
    float m0 = -1e30f, m1 = -1e30f, l0 = 0.f, l1 = 0.f;

    const int ktmax = 2 * qt + 1;
    const int row_g0 = qt * 128 + warp * 16 + r0;

    float4 kst[4], vst[4];

    for (int kt = 0; kt <= ktmax; ++kt) {
        const int buf = kt & 1;
        const uint32_t* Ks = fsm + buf * 8960;
        const uint32_t* Vs = fsm + buf * 8960 + 4352;

        // prefetch next tile into registers (overlaps with compute)
        if (kt < ktmax) {
            const float* kbt = kb + (size_t)((kt + 1) * 64) * CQKV;
            const float* vbt = vb + (size_t)((kt + 1) * 64) * CQKV;
#pragma unroll
            for (int i = 0; i < 4; ++i) {
                const int row = srow + i * 16;
                kst[i] = *(const float4*)(kbt + (size_t)row * CQKV + scol);
                vst[i] = *(const float4*)(vbt + (size_t)row * CQKV + scol);
            }
        }

        // ---- S = Q @ K^T ----
        float s[8][4];
#pragma unroll
        for (int nt = 0; nt < 8; ++nt)
#pragma unroll
            for (int v = 0; v < 4; ++v) s[nt][v] = 0.f;

#pragma unroll
        for (int j = 0; j < 8; ++j) {
#pragma unroll
            for (int nt = 0; nt < 8; ++nt) {
                const int base = (nt * 8 + r0) * SK + j * 8 + q;
                mma8(s[nt], qa[j][0], qa[j][1], qa[j][2], qa[j][3],
                     Ks[base], Ks[base + 4]);
            }
        }

        // ---- causal mask (only last two kt tiles can touch the diagonal) ----
        if (kt >= 2 * qt) {
            const int cb = kt * 64 + 2 * q;
#pragma unroll
            for (int nt = 0; nt < 8; ++nt) {
                const int c = cb + nt * 8;
                if (c     > row_g0)     s[nt][0] = -1e30f;
                if (c + 1 > row_g0)     s[nt][1] = -1e30f;
                if (c     > row_g0 + 8) s[nt][2] = -1e30f;
                if (c + 1 > row_g0 + 8) s[nt][3] = -1e30f;
            }
        }

        // ---- online softmax ----
        float mx0 = -1e30f, mx1 = -1e30f;
#pragma unroll
        for (int nt = 0; nt < 8; ++nt) {
            mx0 = fmaxf(mx0, fmaxf(s[nt][0], s[nt][1]));
            mx1 = fmaxf(mx1, fmaxf(s[nt][2], s[nt][3]));
        }
        mx0 = fmaxf(mx0, __shfl_xor_sync(0xffffffffu, mx0, 1));
        mx0 = fmaxf(mx0, __shfl_xor_sync(0xffffffffu, mx0, 2));
        mx1 = fmaxf(mx1, __shfl_xor_sync(0xffffffffu, mx1, 1));
        mx1 = fmaxf(mx1, __shfl_xor_sync(0xffffffffu, mx1, 2));

        const float mn0 = fmaxf(m0, mx0);
        const float mn1 = fmaxf(m1, mx1);
        float sum0 = 0.f, sum1 = 0.f;
#pragma unroll
        for (int nt = 0; nt < 8; ++nt) {
            s[nt][0] = __expf(s[nt][0] - mn0);
            s[nt][1] = __expf(s[nt][1] - mn0);
            s[nt][2] = __expf(s[nt][2] - mn1);
            s[nt][3] = __expf(s[nt][3] - mn1);
            sum0 += s[nt][0] + s[nt][1];
            sum1 += s[nt][2] + s[nt][3];
        }
        sum0 += __shfl_xor_sync(0xffffffffu, sum0, 1);
        sum0 += __shfl_xor_sync(0xffffffffu, sum0, 2);
        sum1 += __shfl_xor_sync(0xffffffffu, sum1, 1);
        sum1 += __shfl_xor_sync(0xffffffffu, sum1, 2);

        const float al0 = __expf(m0 - mn0);
        const float al1 = __expf(m1 - mn1);
        m0 = mn0; m1 = mn1;
        l0 = l0 * al0 + sum0;
        l1 = l1 * al1 + sum1;
#pragma unroll
        for (int t = 0; t < 8; ++t) {
            o[t][0] *= al0; o[t][1] *= al0;
            o[t][2] *= al1; o[t][3] *= al1;
        }

        // ---- O += P @ V ; P fragments via intra-quad shuffles ----
        const int src_lo = (lane & ~3) | (q >> 1);
        const int src_hi = src_lo + 2;
#pragma unroll
        for (int j = 0; j < 8; ++j) {
            const uint32_t p0 = f2tf(s[j][0]);
            const uint32_t p1 = f2tf(s[j][1]);
            const uint32_t p2 = f2tf(s[j][2]);
            const uint32_t p3 = f2tf(s[j][3]);
            const uint32_t t00 = __shfl_sync(0xffffffffu, p0, src_lo);
            const uint32_t t01 = __shfl_sync(0xffffffffu, p1, src_lo);
            const uint32_t t20 = __shfl_sync(0xffffffffu, p2, src_lo);
            const uint32_t t21 = __shfl_sync(0xffffffffu, p3, src_lo);
            const uint32_t t40 = __shfl_sync(0xffffffffu, p0, src_hi);
            const uint32_t t41 = __shfl_sync(0xffffffffu, p1, src_hi);
            const uint32_t t60 = __shfl_sync(0xffffffffu, p2, src_hi);
            const uint32_t t61 = __shfl_sync(0xffffffffu, p3, src_hi);
            const uint32_t a0 = (q & 1) ? t01 : t00;
            const uint32_t a1 = (q & 1) ? t21 : t20;
            const uint32_t a2 = (q & 1) ? t41 : t40;
            const uint32_t a3 = (q & 1) ? t61 : t60;
#pragma unroll
            for (int dt = 0; dt < 8; ++dt) {
                const uint32_t b0 = Vs[(j * 8 + q) * SV + dt * 8 + r0];
                const uint32_t b1 = Vs[(j * 8 + 4 + q) * SV + dt * 8 + r0];
                mma8(o[dt], a0, a1, a2, a3, b0, b1);
            }
        }

        // ---- stage prefetched tile into the other buffer ----
        if (kt < ktmax) {
            uint32_t* Kn = fsm + ((kt + 1) & 1) * 8960;
            uint32_t* Vn = Kn + 4352;
#pragma unroll
            for (int i = 0; i < 4; ++i) {
                const int row = srow + i * 16;
                uint4 t = { f2tf(kst[i].x), f2tf(kst[i].y), f2tf(kst[i].z), f2tf(kst[i].w) };
                *(uint4*)&Kn[row * SK + scol] = t;
                uint4 u = { f2tf(vst[i].x), f2tf(vst[i].y), f2tf(vst[i].z), f2tf(vst[i].w) };
                *(uint4*)&Vn[row * SV + scol] = u;
            }
        }
        __syncthreads();
    }

    // ---- epilogue: normalize, write [B,N,H,HD] ----
    {
        const float il0 = 1.f / l0;
        const float il1 = 1.f / l1;
        float* ob = out + ((size_t)b * NN + (size_t)qt * 128 + warp * 16 + r0) * DD + h * HDIM;
#pragma unroll
        for (int dt = 0; dt < 8; ++dt) {
            float2 v0 = { o[dt][0] * il0, o[dt][1] * il0 };
            float2 v1 = { o[dt][2] * il1, o[dt][3] * il1 };
            *(float2*)(ob + dt * 8 + 2 * q) = v0;
            *(float2*)(ob + (size_t)8 * DD + dt * 8 + 2 * q) = v1;
        }
    }
}

// ---------------------------------------------------------------------------
extern "C" void kernel_launch(void* const* d_in, const int* in_sizes, int n_in,
                              void* d_out, int out_size)
{
    (void)in_sizes; (void)n_in; (void)out_size;
    const float* x    = (const float*)d_in[0];
    const float* Wqkv = (const float*)d_in[1];
    const float* bqkv = (const float*)d_in[2];
    const float* Wout = (const float*)d_in[3];
    const float* bout = (const float*)d_in[4];
    float* out = (float*)d_out;

    float *qkv, *attn;
    cudaGetSymbolAddress((void**)&qkv, g_qkv);
    cudaGetSymbolAddress((void**)&attn, g_attn);

    static int set_attr = 0;
    if (!set_attr) {
        cudaFuncSetAttribute(gemm_tf32,
                             cudaFuncAttributeMaxDynamicSharedMemorySize,
                             GEMM_SMEM);
        cudaFuncSetAttribute(flash_tf32,
                             cudaFuncAttributeMaxDynamicSharedMemorySize,
                             FLASH_SMEM);
        set_attr = 1;
    }

    // 1) QKV projection: [8192,512] @ [512,1536] + bias
    {
        dim3 grid(CQKV / 128, (BB * NN) / 128);
        gemm_tf32<<<grid, 256, GEMM_SMEM>>>(x, Wqkv, bqkv, qkv, BB * NN, CQKV, DD);
    }

    // 2) causal flash attention (TF32 tensor cores, BM=128)
    {
        flash_tf32<<<512, 256, FLASH_SMEM>>>(qkv, attn);
    }

    // 3) output projection: [8192,512] @ [512,512] + bias
    {
        dim3 grid(DD / 128, (BB * NN) / 128);
        gemm_tf32<<<grid, 256, GEMM_SMEM>>>(attn, Wout, bout, out, BB * NN, DD, DD);
    }
}

// round 4
// speedup vs baseline: 6.5214x; 1.7844x over previous
#include <cuda_runtime.h>
#include <cuda_fp16.h>
#include <stdint.h>

#define BB   2
#define NN   4096
#define DD   512
#define HH   8
#define HDIM 64
#define CQKV 1536

// Scratch (static device arrays — no runtime allocation), fp16
__device__ __half g_qkv[(size_t)BB * NN * CQKV];   // [B,N,3,H,HD]
__device__ __half g_attn[(size_t)BB * NN * DD];    // [B,N,D]

// ---------------------------------------------------------------------------
// helpers
// ---------------------------------------------------------------------------
__device__ __forceinline__ uint32_t packh2(float lo, float hi) {
    __half2 h = __floats2half2_rn(lo, hi);
    return *(uint32_t*)&h;
}

__device__ __forceinline__ void mma16(float* c,
    uint32_t a0, uint32_t a1, uint32_t a2, uint32_t a3,
    uint32_t b0, uint32_t b1)
{
    asm volatile(
        "mma.sync.aligned.m16n8k16.row.col.f32.f16.f16.f32 "
        "{%0,%1,%2,%3}, {%4,%5,%6,%7}, {%8,%9}, {%0,%1,%2,%3};"
        : "+f"(c[0]), "+f"(c[1]), "+f"(c[2]), "+f"(c[3])
        : "r"(a0), "r"(a1), "r"(a2), "r"(a3), "r"(b0), "r"(b1));
}

// ---------------------------------------------------------------------------
// fp16 GEMM, fused bias, double-buffered smem + register prefetch.
// BM=128, BN=128, BK=32, 256 threads (8 warps 2x4), warp tile 64x32.
// smem (uint32 words): As 128*20=2560, Bs 16*136=2176; x2 buffers = 9472 words.
// A_HALF: A operand is fp16 (else fp32). C_HALF: output fp16 (else fp32).
// ---------------------------------------------------------------------------
#define STA 20
#define STB 136
#define GEMM_BUF 4736
#define GEMM_SMEM (2 * GEMM_BUF * 4)

template<bool A_HALF, bool C_HALF>
__global__ __launch_bounds__(256, 2) void gemm_h(
    const void* __restrict__ Ap, const float* __restrict__ W,
    const float* __restrict__ bias, void* __restrict__ Cp,
    int M, int Nc, int K)
{
    extern __shared__ uint32_t gsm[];

    const int tid  = threadIdx.x;
    const int lane = tid & 31;
    const int warp = tid >> 5;
    const int wm = warp >> 2;
    const int wn = warp & 3;
    const int r0 = lane >> 2;
    const int q  = lane & 3;
    const int row0 = blockIdx.y * 128;
    const int col0 = blockIdx.x * 128;

    const int ar = tid >> 3;           // 0..31 (x4 -> 128 rows)
    const int ac = (tid & 7) * 4;      // k offset, 0..28
    const int br = tid >> 5;           // 0..7 (k'-groups, x2 -> 16)
    const int bc = (tid & 31) * 4;     // n offset, 0..124

    const float*  Af = (const float*)Ap;
    const __half* Ah = (const __half*)Ap;
    const float*  Wg = W + col0 + bc;

    float acc[4][4][4];
#pragma unroll
    for (int i = 0; i < 4; ++i)
#pragma unroll
        for (int j = 0; j < 4; ++j)
#pragma unroll
            for (int v = 0; v < 4; ++v) acc[i][j][v] = 0.f;

    float4 a_f[4]; uint2 a_h[4];
    float4 b_lo[2], b_hi[2];

    // prefetch k0 = 0
#pragma unroll
    for (int i = 0; i < 4; ++i) {
        if (A_HALF) a_h[i] = *(const uint2*)(Ah + (size_t)(row0 + ar + i * 32) * K + ac);
        else        a_f[i] = *(const float4*)(Af + (size_t)(row0 + ar + i * 32) * K + ac);
    }
#pragma unroll
    for (int i = 0; i < 2; ++i) {
        const int kp = 2 * (br + i * 8);
        b_lo[i] = *(const float4*)(Wg + (size_t)kp * Nc);
        b_hi[i] = *(const float4*)(Wg + (size_t)(kp + 1) * Nc);
    }

    // stage buffer 0
    {
        uint32_t* As = gsm;
        uint32_t* Bs = gsm + 2560;
#pragma unroll
        for (int i = 0; i < 4; ++i) {
            uint2 t;
            if (A_HALF) t = a_h[i];
            else        t = make_uint2(packh2(a_f[i].x, a_f[i].y), packh2(a_f[i].z, a_f[i].w));
            *(uint2*)&As[(ar + i * 32) * STA + ac / 2] = t;
        }
#pragma unroll
        for (int i = 0; i < 2; ++i) {
            uint4 t = { packh2(b_lo[i].x, b_hi[i].x), packh2(b_lo[i].y, b_hi[i].y),
                        packh2(b_lo[i].z, b_hi[i].z), packh2(b_lo[i].w, b_hi[i].w) };
            *(uint4*)&Bs[(br + i * 8) * STB + bc] = t;
        }
    }
    __syncthreads();

    const int nk = K >> 5;
    for (int it = 0; it < nk; ++it) {
        const uint32_t* As = gsm + (it & 1) * GEMM_BUF;
        const uint32_t* Bs = As + 2560;

        if (it + 1 < nk) {
            const int k0 = (it + 1) * 32;
#pragma unroll
            for (int i = 0; i < 4; ++i) {
                if (A_HALF) a_h[i] = *(const uint2*)(Ah + (size_t)(row0 + ar + i * 32) * K + k0 + ac);
                else        a_f[i] = *(const float4*)(Af + (size_t)(row0 + ar + i * 32) * K + k0 + ac);
            }
#pragma unroll
            for (int i = 0; i < 2; ++i) {
                const int kp = k0 + 2 * (br + i * 8);
                b_lo[i] = *(const float4*)(Wg + (size_t)kp * Nc);
                b_hi[i] = *(const float4*)(Wg + (size_t)(kp + 1) * Nc);
            }
        }

#pragma unroll
        for (int kk = 0; kk < 2; ++kk) {
            uint32_t a[4][4], b[4][2];
#pragma unroll
            for (int mt = 0; mt < 4; ++mt) {
                const int base = (wm * 64 + mt * 16 + r0) * STA + kk * 8 + q;
                a[mt][0] = As[base];
                a[mt][1] = As[base + 8 * STA];
                a[mt][2] = As[base + 4];
                a[mt][3] = As[base + 8 * STA + 4];
            }
#pragma unroll
            for (int nt = 0; nt < 4; ++nt) {
                const int nb = wn * 32 + nt * 8 + r0;
                b[nt][0] = Bs[(kk * 8 + q) * STB + nb];
                b[nt][1] = Bs[(kk * 8 + 4 + q) * STB + nb];
            }
#pragma unroll
            for (int mt = 0; mt < 4; ++mt)
#pragma unroll
                for (int nt = 0; nt < 4; ++nt)
                    mma16(acc[mt][nt], a[mt][0], a[mt][1], a[mt][2], a[mt][3],
                          b[nt][0], b[nt][1]);
        }

        if (it + 1 < nk) {
            uint32_t* Asn = gsm + ((it + 1) & 1) * GEMM_BUF;
            uint32_t* Bsn = Asn + 2560;
#pragma unroll
            for (int i = 0; i < 4; ++i) {
                uint2 t;
                if (A_HALF) t = a_h[i];
                else        t = make_uint2(packh2(a_f[i].x, a_f[i].y), packh2(a_f[i].z, a_f[i].w));
                *(uint2*)&Asn[(ar + i * 32) * STA + ac / 2] = t;
            }
#pragma unroll
            for (int i = 0; i < 2; ++i) {
                uint4 t = { packh2(b_lo[i].x, b_hi[i].x), packh2(b_lo[i].y, b_hi[i].y),
                            packh2(b_lo[i].z, b_hi[i].z), packh2(b_lo[i].w, b_hi[i].w) };
                *(uint4*)&Bsn[(br + i * 8) * STB + bc] = t;
            }
        }
        __syncthreads();
    }

    // epilogue: bias + store
#pragma unroll
    for (int mt = 0; mt < 4; ++mt) {
        const int r = row0 + wm * 64 + mt * 16 + r0;
#pragma unroll
        for (int nt = 0; nt < 4; ++nt) {
            const int c = col0 + wn * 32 + nt * 8 + 2 * q;
            const float bx = bias[c], by = bias[c + 1];
            if (C_HALF) {
                __half* Ch = (__half*)Cp;
                *(uint32_t*)(Ch + (size_t)r * Nc + c)       = packh2(acc[mt][nt][0] + bx, acc[mt][nt][1] + by);
                *(uint32_t*)(Ch + (size_t)(r + 8) * Nc + c) = packh2(acc[mt][nt][2] + bx, acc[mt][nt][3] + by);
            } else {
                float* Cf = (float*)Cp;
                float2 v0 = { acc[mt][nt][0] + bx, acc[mt][nt][1] + by };
                float2 v1 = { acc[mt][nt][2] + bx, acc[mt][nt][3] + by };
                *(float2*)&Cf[(size_t)r * Nc + c] = v0;
                *(float2*)&Cf[(size_t)(r + 8) * Nc + c] = v1;
            }
        }
    }
}

// ---------------------------------------------------------------------------
// Flash attention fp16: BM=128 (8 warps), BN=64, double-buffered K/V smem,
// register prefetch, one sync per tile. P->A conversion is register-local
// (m16n8k16 A-layout == C-layout). smem words: Ks 64x36=2304, Vs 32x72=2304
// per buffer; Qs (128x36=4608) aliases buffer 1. Total 9216 words = 36864 B.
// ---------------------------------------------------------------------------
#define STK 36
#define STV 72
#define STQ 36
#define FLASH_SMEM (9216 * 4)

__global__ __launch_bounds__(256, 2) void flash_h(
    const __half* __restrict__ qkv, __half* __restrict__ outh)
{
    extern __shared__ uint32_t fsm[];
    uint32_t* Qs = fsm + 4608;   // alias over buffer 1

    const int tid  = threadIdx.x;
    const int lane = tid & 31;
    const int warp = tid >> 5;
    const int r0 = lane >> 2;
    const int q  = lane & 3;

    const int idx = blockIdx.x;          // 0..511, heavy qt first
    const int qt  = 31 - (idx >> 4);
    const int h   = idx & 7;
    const int b   = (idx >> 3) & 1;
    const float scale = 0.125f;

    // staging geometry
    const int krow = tid >> 2;           // 0..63
    const int kch  = (tid & 3) * 4;      // uint32 offset (halves offset = *2)
    const int vk   = tid >> 3;           // 0..31 (key pair index)
    const int vd   = (tid & 7) * 8;      // d offset (halves == uint32 idx in Vs)

    const __half* kb = qkv + (size_t)b * NN * CQKV + DD + h * HDIM;
    const __half* vb = qkv + (size_t)b * NN * CQKV + 2 * DD + h * HDIM;
    const __half* qb = qkv + ((size_t)b * NN + (size_t)qt * 128) * CQKV + h * HDIM;

    // ---- stage Q (pure copy) ----
#pragma unroll
    for (int i = 0; i < 2; ++i) {
        const int row = krow + i * 64;
        uint4 u0 = *(const uint4*)(qb + (size_t)row * CQKV + kch * 2);
        uint4 u1 = *(const uint4*)(qb + (size_t)row * CQKV + kch * 2 + 32);
        *(uint4*)&Qs[row * STQ + kch]      = u0;
        *(uint4*)&Qs[row * STQ + kch + 16] = u1;
    }
    // ---- stage K0 (copy) / V0 (PRMT interleave key-pairs) ----
    {
        uint4 u0 = *(const uint4*)(kb + (size_t)krow * CQKV + kch * 2);
        uint4 u1 = *(const uint4*)(kb + (size_t)krow * CQKV + kch * 2 + 32);
        *(uint4*)&fsm[krow * STK + kch]      = u0;
        *(uint4*)&fsm[krow * STK + kch + 16] = u1;

        uint4 lo = *(const uint4*)(vb + (size_t)(2 * vk) * CQKV + vd);
        uint4 hi = *(const uint4*)(vb + (size_t)(2 * vk + 1) * CQKV + vd);
        uint32_t* Vs0 = fsm + 2304 + vk * STV + vd;
        Vs0[0] = __byte_perm(lo.x, hi.x, 0x5410); Vs0[1] = __byte_perm(lo.x, hi.x, 0x7632);
        Vs0[2] = __byte_perm(lo.y, hi.y, 0x5410); Vs0[3] = __byte_perm(lo.y, hi.y, 0x7632);
        Vs0[4] = __byte_perm(lo.z, hi.z, 0x5410); Vs0[5] = __byte_perm(lo.z, hi.z, 0x7632);
        Vs0[6] = __byte_perm(lo.w, hi.w, 0x5410); Vs0[7] = __byte_perm(lo.w, hi.w, 0x7632);
    }
    __syncthreads();

    // ---- preload Q A-fragments (4 k16-blocks) ----
    uint32_t qa[4][4];
    {
        const int mrow = warp * 16 + r0;
#pragma unroll
        for (int kk = 0; kk < 4; ++kk) {
            const int base = mrow * STQ + kk * 8 + q;
            qa[kk][0] = Qs[base];
            qa[kk][1] = Qs[base + 8 * STQ];
            qa[kk][2] = Qs[base + 4];
            qa[kk][3] = Qs[base + 8 * STQ + 4];
        }
    }
    __syncthreads();   // Qs region now free for buffer 1

    float o[8][4];
#pragma unroll
    for (int t = 0; t < 8; ++t)
#pragma unroll
        for (int v = 0; v < 4; ++v) o[t][v] = 0.f;
    float m0 = -1e30f, m1 = -1e30f, l0 = 0.f, l1 = 0.f;

    const int ktmax = 2 * qt + 1;
    const int row_g0 = qt * 128 + warp * 16 + r0;

    uint4 k_st0, k_st1, v_lo, v_hi;

    for (int kt = 0; kt <= ktmax; ++kt) {
        const uint32_t* Ks = fsm + (kt & 1) * 4608;
        const uint32_t* Vs = Ks + 2304;

        // prefetch next tile into registers
        if (kt < ktmax) {
            const __half* kbt = kb + (size_t)((kt + 1) * 64) * CQKV;
            const __half* vbt = vb + (size_t)((kt + 1) * 64) * CQKV;
            k_st0 = *(const uint4*)(kbt + (size_t)krow * CQKV + kch * 2);
            k_st1 = *(const uint4*)(kbt + (size_t)krow * CQKV + kch * 2 + 32);
            v_lo  = *(const uint4*)(vbt + (size_t)(2 * vk) * CQKV + vd);
            v_hi  = *(const uint4*)(vbt + (size_t)(2 * vk + 1) * CQKV + vd);
        }

        // ---- S = Q @ K^T ----
        float s[8][4];
#pragma unroll
        for (int nt = 0; nt < 8; ++nt)
#pragma unroll
            for (int v = 0; v < 4; ++v) s[nt][v] = 0.f;

#pragma unroll
        for (int kk = 0; kk < 4; ++kk) {
#pragma unroll
            for (int nt = 0; nt < 8; ++nt) {
                const int base = (nt * 8 + r0) * STK + kk * 8 + q;
                mma16(s[nt], qa[kk][0], qa[kk][1], qa[kk][2], qa[kk][3],
                      Ks[base], Ks[base + 4]);
            }
        }

        // scale
#pragma unroll
        for (int nt = 0; nt < 8; ++nt) {
            s[nt][0] *= scale; s[nt][1] *= scale;
            s[nt][2] *= scale; s[nt][3] *= scale;
        }

        // ---- causal mask (only near-diagonal tiles) ----
        if (kt >= 2 * qt) {
            const int cb = kt * 64 + 2 * q;
#pragma unroll
            for (int nt = 0; nt < 8; ++nt) {
                const int c = cb + nt * 8;
                if (c     > row_g0)     s[nt][0] = -1e30f;
                if (c + 1 > row_g0)     s[nt][1] = -1e30f;
                if (c     > row_g0 + 8) s[nt][2] = -1e30f;
                if (c + 1 > row_g0 + 8) s[nt][3] = -1e30f;
            }
        }

        // ---- online softmax ----
        float mx0 = -1e30f, mx1 = -1e30f;
#pragma unroll
        for (int nt = 0; nt < 8; ++nt) {
            mx0 = fmaxf(mx0, fmaxf(s[nt][0], s[nt][1]));
            mx1 = fmaxf(mx1, fmaxf(s[nt][2], s[nt][3]));
        }
        mx0 = fmaxf(mx0, __shfl_xor_sync(0xffffffffu, mx0, 1));
        mx0 = fmaxf(mx0, __shfl_xor_sync(0xffffffffu, mx0, 2));
        mx1 = fmaxf(mx1, __shfl_xor_sync(0xffffffffu, mx1, 1));
        mx1 = fmaxf(mx1, __shfl_xor_sync(0xffffffffu, mx1, 2));

        const float mn0 = fmaxf(m0, mx0);
        const float mn1 = fmaxf(m1, mx1);
        float sum0 = 0.f, sum1 = 0.f;
#pragma unroll
        for (int nt = 0; nt < 8; ++nt) {
            s[nt][0] = __expf(s[nt][0] - mn0);
            s[nt][1] = __expf(s[nt][1] - mn0);
            s[nt][2] = __expf(s[nt][2] - mn1);
            s[nt][3] = __expf(s[nt][3] - mn1);
            sum0 += s[nt][0] + s[nt][1];
            sum1 += s[nt][2] + s[nt][3];
        }
        sum0 += __shfl_xor_sync(0xffffffffu, sum0, 1);
        sum0 += __shfl_xor_sync(0xffffffffu, sum0, 2);
        sum1 += __shfl_xor_sync(0xffffffffu, sum1, 1);
        sum1 += __shfl_xor_sync(0xffffffffu, sum1, 2);

        const float al0 = __expf(m0 - mn0);
        const float al1 = __expf(m1 - mn1);
        m0 = mn0; m1 = mn1;
        l0 = l0 * al0 + sum0;
        l1 = l1 * al1 + sum1;
#pragma unroll
        for (int t = 0; t < 8; ++t) {
            o[t][0] *= al0; o[t][1] *= al0;
            o[t][2] *= al1; o[t][3] *= al1;
        }

        // ---- O += P @ V ; A-frags are register-local packs of s ----
#pragma unroll
        for (int kk = 0; kk < 4; ++kk) {
            const uint32_t a0 = packh2(s[2 * kk][0],     s[2 * kk][1]);
            const uint32_t a1 = packh2(s[2 * kk][2],     s[2 * kk][3]);
            const uint32_t a2 = packh2(s[2 * kk + 1][0], s[2 * kk + 1][1]);
            const uint32_t a3 = packh2(s[2 * kk + 1][2], s[2 * kk + 1][3]);
#pragma unroll
            for (int dt = 0; dt < 8; ++dt) {
                const uint32_t b0 = Vs[(kk * 8 + q) * STV + dt * 8 + r0];
                const uint32_t b1 = Vs[(kk * 8 + 4 + q) * STV + dt * 8 + r0];
                mma16(o[dt], a0, a1, a2, a3, b0, b1);
            }
        }

        // ---- stage prefetched tile into other buffer ----
        if (kt < ktmax) {
            uint32_t* Kn = fsm + ((kt + 1) & 1) * 4608;
            uint32_t* Vn = Kn + 2304 + vk * STV + vd;
            *(uint4*)&Kn[krow * STK + kch]      = k_st0;
            *(uint4*)&Kn[krow * STK + kch + 16] = k_st1;
            Vn[0] = __byte_perm(v_lo.x, v_hi.x, 0x5410); Vn[1] = __byte_perm(v_lo.x, v_hi.x, 0x7632);
            Vn[2] = __byte_perm(v_lo.y, v_hi.y, 0x5410); Vn[3] = __byte_perm(v_lo.y, v_hi.y, 0x7632);
            Vn[4] = __byte_perm(v_lo.z, v_hi.z, 0x5410); Vn[5] = __byte_perm(v_lo.z, v_hi.z, 0x7632);
            Vn[6] = __byte_perm(v_lo.w, v_hi.w, 0x5410); Vn[7] = __byte_perm(v_lo.w, v_hi.w, 0x7632);
        }
        __syncthreads();
    }

    // ---- epilogue: normalize, write fp16 [B,N,H,HD] ----
    {
        const float il0 = 1.f / l0;
        const float il1 = 1.f / l1;
        __half* ob = outh + ((size_t)b * NN + (size_t)qt * 128 + warp * 16 + r0) * DD + h * HDIM;
#pragma unroll
        for (int dt = 0; dt < 8; ++dt) {
            *(uint32_t*)(ob + dt * 8 + 2 * q) =
                packh2(o[dt][0] * il0, o[dt][1] * il0);
            *(uint32_t*)(ob + (size_t)8 * DD + dt * 8 + 2 * q) =
                packh2(o[dt][2] * il1, o[dt][3] * il1);
        }
    }
}

// ---------------------------------------------------------------------------
extern "C" void kernel_launch(void* const* d_in, const int* in_sizes, int n_in,
                              void* d_out, int out_size)
{
    (void)in_sizes; (void)n_in; (void)out_size;
    const float* x    = (const float*)d_in[0];
    const float* Wqkv = (const float*)d_in[1];
    const float* bqkv = (const float*)d_in[2];
    const float* Wout = (const float*)d_in[3];
    const float* bout = (const float*)d_in[4];
    float* out = (float*)d_out;

    __half *qkv, *attn;
    cudaGetSymbolAddress((void**)&qkv, g_qkv);
    cudaGetSymbolAddress((void**)&attn, g_attn);

    // 1) QKV projection: fp32 x @ fp32 W -> fp16 qkv
    {
        dim3 grid(CQKV / 128, (BB * NN) / 128);
        gemm_h<false, true><<<grid, 256, GEMM_SMEM>>>(x, Wqkv, bqkv, qkv,
                                                      BB * NN, CQKV, DD);
    }

    // 2) causal flash attention (fp16 mma)
    {
        flash_h<<<512, 256, FLASH_SMEM>>>(qkv, attn);
    }

    // 3) output projection: fp16 attn @ fp32 W -> fp32 out
    {
        dim3 grid(DD / 128, (BB * NN) / 128);
        gemm_h<true, false><<<grid, 256, GEMM_SMEM>>>(attn, Wout, bout, out,
                                                      BB * NN, DD, DD);
    }
}

// round 5
// speedup vs baseline: 7.2464x; 1.1112x over previous
#include <cuda_runtime.h>
#include <cuda_fp16.h>
#include <stdint.h>

#define BB   2
#define NN   4096
#define DD   512
#define HH   8
#define HDIM 64
#define CQKV 1536

// Scratch (static device arrays — no runtime allocation)
__device__ __half g_qkv[(size_t)BB * NN * CQKV];    // [B,N,3,H,HD]
__device__ __half g_attn[(size_t)BB * NN * DD];     // [B,N,D]
__device__ __half g_xh[(size_t)BB * NN * DD];       // fp16 copy of x
__device__ __half g_wqkvh[(size_t)DD * CQKV];       // fp16 copy of W_qkv
__device__ __half g_wouth[(size_t)DD * DD];         // fp16 copy of W_out

// ---------------------------------------------------------------------------
// helpers
// ---------------------------------------------------------------------------
__device__ __forceinline__ uint32_t packh2(float lo, float hi) {
    __half2 h = __floats2half2_rn(lo, hi);
    return *(uint32_t*)&h;
}

__device__ __forceinline__ void mma16(float* c,
    uint32_t a0, uint32_t a1, uint32_t a2, uint32_t a3,
    uint32_t b0, uint32_t b1)
{
    asm volatile(
        "mma.sync.aligned.m16n8k16.row.col.f32.f16.f16.f32 "
        "{%0,%1,%2,%3}, {%4,%5,%6,%7}, {%8,%9}, {%0,%1,%2,%3};"
        : "+f"(c[0]), "+f"(c[1]), "+f"(c[2]), "+f"(c[3])
        : "r"(a0), "r"(a1), "r"(a2), "r"(a3), "r"(b0), "r"(b1));
}

__device__ __forceinline__ void cp16(uint32_t dst, const void* src) {
    asm volatile("cp.async.cg.shared.global [%0], [%1], 16;"
                 :: "r"(dst), "l"(src));
}
#define CP_COMMIT() asm volatile("cp.async.commit_group;")
#define CP_WAIT0()  asm volatile("cp.async.wait_group 0;")

__device__ __forceinline__ void ldsm4(uint32_t& r0, uint32_t& r1,
                                      uint32_t& r2, uint32_t& r3, uint32_t a) {
    asm volatile("ldmatrix.sync.aligned.m8n8.x4.shared.b16 {%0,%1,%2,%3}, [%4];"
        : "=r"(r0), "=r"(r1), "=r"(r2), "=r"(r3) : "r"(a));
}
__device__ __forceinline__ void ldsm4t(uint32_t& r0, uint32_t& r1,
                                       uint32_t& r2, uint32_t& r3, uint32_t a) {
    asm volatile("ldmatrix.sync.aligned.m8n8.x4.trans.shared.b16 {%0,%1,%2,%3}, [%4];"
        : "=r"(r0), "=r"(r1), "=r"(r2), "=r"(r3) : "r"(a));
}

// ---------------------------------------------------------------------------
// fp32 -> fp16 conversion (one-time)
// ---------------------------------------------------------------------------
__global__ __launch_bounds__(256) void f2h_kernel(
    const float4* __restrict__ src, uint2* __restrict__ dst, int n4)
{
    const int i = blockIdx.x * 256 + threadIdx.x;
    if (i < n4) {
        float4 v = src[i];
        dst[i] = make_uint2(packh2(v.x, v.y), packh2(v.z, v.w));
    }
}

// ---------------------------------------------------------------------------
// fp16 GEMM: C = A[M,K] @ W[K,N] + bias. All-fp16 operands, fp32 accum.
// BM=128, BN=128, BK=32, 256 thr (8 warps 2x4), warp tile 64x32.
// cp.async double buffer + ldmatrix fragments.
// smem bytes: A 128x80=10240, B 32x272=8704; buffer stride 18944; x2 = 37888.
// ---------------------------------------------------------------------------
#define GEMM_BUFB 18944
#define GEMM_SMEM (2 * GEMM_BUFB)

template<bool C_HALF>
__global__ __launch_bounds__(256, 2) void gemm_h(
    const __half* __restrict__ A, const __half* __restrict__ W,
    const float* __restrict__ bias, void* __restrict__ Cp,
    int M, int Nc, int K)
{
    extern __shared__ char gsm[];
    const uint32_t sb = (uint32_t)__cvta_generic_to_shared(gsm);

    const int tid  = threadIdx.x;
    const int lane = tid & 31;
    const int warp = tid >> 5;
    const int wm = warp >> 2;
    const int wn = warp & 3;
    const int r0 = lane >> 2;
    const int q  = lane & 3;
    const int row0 = blockIdx.y * 128;
    const int col0 = blockIdx.x * 128;

    // cp.async staging geometry
    const int arow = tid >> 2;        // 0..63 (+64)
    const int adc  = tid & 3;         // 16B chunk in k
    const int brow = tid >> 4;        // 0..15 (+16)
    const int bnc  = tid & 15;        // 16B chunk in n

    const __half* Ag = A + (size_t)(row0 + arow) * K + adc * 8;
    const __half* Wg = W + (size_t)brow * Nc + col0 + bnc * 8;

    // fragment base addresses
    const uint32_t a_base = sb + (wm * 64 + (lane & 15)) * 80 + (lane >> 4) * 16;
    const uint32_t b_base = sb + 10240 +
        ((lane & 7) + ((lane >> 3) & 1) * 8) * 272 + wn * 64 + (lane >> 4) * 16;

    float acc[4][4][4];
#pragma unroll
    for (int i = 0; i < 4; ++i)
#pragma unroll
        for (int j = 0; j < 4; ++j)
#pragma unroll
            for (int v = 0; v < 4; ++v) acc[i][j][v] = 0.f;

    // stage buffer 0 (k0 = 0)
    {
        cp16(sb + arow * 80 + adc * 16, Ag);
        cp16(sb + (arow + 64) * 80 + adc * 16, Ag + (size_t)64 * K);
        cp16(sb + 10240 + brow * 272 + bnc * 16, Wg);
        cp16(sb + 10240 + (brow + 16) * 272 + bnc * 16, Wg + (size_t)16 * Nc);
    }
    CP_COMMIT();
    CP_WAIT0();
    __syncthreads();

    const int nk = K >> 5;
    for (int it = 0; it < nk; ++it) {
        const uint32_t bufo = (uint32_t)(it & 1) * GEMM_BUFB;

        if (it + 1 < nk) {
            const int k0 = (it + 1) * 32;
            const uint32_t nb = (uint32_t)((it + 1) & 1) * GEMM_BUFB;
            cp16(sb + nb + arow * 80 + adc * 16, Ag + k0);
            cp16(sb + nb + (arow + 64) * 80 + adc * 16, Ag + (size_t)64 * K + k0);
            cp16(sb + nb + 10240 + brow * 272 + bnc * 16, Wg + (size_t)k0 * Nc);
            cp16(sb + nb + 10240 + (brow + 16) * 272 + bnc * 16,
                 Wg + (size_t)(k0 + 16) * Nc);
            CP_COMMIT();
        }

#pragma unroll
        for (int kk = 0; kk < 2; ++kk) {
            uint32_t a[4][4];
#pragma unroll
            for (int mt = 0; mt < 4; ++mt)
                ldsm4(a[mt][0], a[mt][1], a[mt][2], a[mt][3],
                      a_base + bufo + mt * 1280 + kk * 32);
#pragma unroll
            for (int ntp = 0; ntp < 2; ++ntp) {
                uint32_t b0, b1, b2, b3;
                ldsm4t(b0, b1, b2, b3, b_base + bufo + kk * 4352 + ntp * 32);
#pragma unroll
                for (int mt = 0; mt < 4; ++mt) {
                    mma16(acc[mt][2 * ntp],     a[mt][0], a[mt][1], a[mt][2], a[mt][3], b0, b1);
                    mma16(acc[mt][2 * ntp + 1], a[mt][0], a[mt][1], a[mt][2], a[mt][3], b2, b3);
                }
            }
        }

        if (it + 1 < nk) CP_WAIT0();
        __syncthreads();
    }

    // epilogue: bias + store
#pragma unroll
    for (int mt = 0; mt < 4; ++mt) {
        const int r = row0 + wm * 64 + mt * 16 + r0;
#pragma unroll
        for (int nt = 0; nt < 4; ++nt) {
            const int c = col0 + wn * 32 + nt * 8 + 2 * q;
            const float bx = bias[c], by = bias[c + 1];
            if (C_HALF) {
                __half* Ch = (__half*)Cp;
                *(uint32_t*)(Ch + (size_t)r * Nc + c)       = packh2(acc[mt][nt][0] + bx, acc[mt][nt][1] + by);
                *(uint32_t*)(Ch + (size_t)(r + 8) * Nc + c) = packh2(acc[mt][nt][2] + bx, acc[mt][nt][3] + by);
            } else {
                float* Cf = (float*)Cp;
                float2 v0 = { acc[mt][nt][0] + bx, acc[mt][nt][1] + by };
                float2 v1 = { acc[mt][nt][2] + bx, acc[mt][nt][3] + by };
                *(float2*)&Cf[(size_t)r * Nc + c] = v0;
                *(float2*)&Cf[(size_t)(r + 8) * Nc + c] = v1;
            }
        }
    }
}

// ---------------------------------------------------------------------------
// Flash attention fp16: BM=128 (8 warps), BN=64. cp.async double-buffered
// K/V (plain row-major, 144B stride), ldmatrix frags (V via .trans — no
// interleave staging). One sync per tile. P->A is register-local.
// smem: K 64x144=9216 + V 9216 per buffer (18432); Q aliases buffer 1.
// ---------------------------------------------------------------------------
#define FLASH_BUFB 18432
#define FLASH_SMEM (2 * FLASH_BUFB)

__global__ __launch_bounds__(256, 2) void flash_h(
    const __half* __restrict__ qkv, __half* __restrict__ outh)
{
    extern __shared__ char fss[];
    const uint32_t sb = (uint32_t)__cvta_generic_to_shared(fss);

    const int tid  = threadIdx.x;
    const int lane = tid & 31;
    const int warp = tid >> 5;
    const int r0 = lane >> 2;
    const int q  = lane & 3;

    const int idx = blockIdx.x;          // heavy qt first
    const int qt  = 31 - (idx >> 4);
    const int h   = idx & 7;
    const int b   = (idx >> 3) & 1;
    const float scale = 0.125f;

    const int srow = tid >> 3;           // 0..31 (+32)
    const int sdc  = tid & 7;            // 16B chunk in d

    const __half* qb = qkv + ((size_t)b * NN + (size_t)qt * 128) * CQKV + h * HDIM;
    const __half* kb = qkv + (size_t)b * NN * CQKV + DD + h * HDIM;
    const __half* vb = qkv + (size_t)b * NN * CQKV + 2 * DD + h * HDIM;

    // ---- prologue staging: Q -> buf1 region, K0/V0 -> buf0 ----
#pragma unroll
    for (int i = 0; i < 4; ++i) {
        const int c = tid + 256 * i;
        const int row = c >> 3, dc = c & 7;
        cp16(sb + FLASH_BUFB + row * 144 + dc * 16, qb + (size_t)row * CQKV + dc * 8);
    }
    {
        cp16(sb + srow * 144 + sdc * 16, kb + (size_t)srow * CQKV + sdc * 8);
        cp16(sb + (srow + 32) * 144 + sdc * 16, kb + (size_t)(srow + 32) * CQKV + sdc * 8);
        cp16(sb + 9216 + srow * 144 + sdc * 16, vb + (size_t)srow * CQKV + sdc * 8);
        cp16(sb + 9216 + (srow + 32) * 144 + sdc * 16, vb + (size_t)(srow + 32) * CQKV + sdc * 8);
    }
    CP_COMMIT();
    CP_WAIT0();
    __syncthreads();

    // ---- preload Q A-fragments ----
    uint32_t qa[4][4];
    {
        const uint32_t q_base = sb + FLASH_BUFB +
            (warp * 16 + (lane & 15)) * 144 + (lane >> 4) * 16;
#pragma unroll
        for (int kk = 0; kk < 4; ++kk)
            ldsm4(qa[kk][0], qa[kk][1], qa[kk][2], qa[kk][3], q_base + kk * 32);
    }
    __syncthreads();   // Q region now reusable as buffer 1

    // fragment bases
    const uint32_t k_base = sb + ((lane & 7) + ((lane >> 3) & 1) * 8) * 144 + (lane >> 4) * 16;
    const uint32_t v_base = k_base + 9216;

    float o[8][4];
#pragma unroll
    for (int t = 0; t < 8; ++t)
#pragma unroll
        for (int v = 0; v < 4; ++v) o[t][v] = 0.f;
    float m0 = -1e30f, m1 = -1e30f, l0 = 0.f, l1 = 0.f;

    const int ktmax = 2 * qt + 1;
    const int row_g0 = qt * 128 + warp * 16 + r0;

    for (int kt = 0; kt <= ktmax; ++kt) {
        const uint32_t bufo = (uint32_t)(kt & 1) * FLASH_BUFB;

        // prefetch next tile via cp.async
        if (kt < ktmax) {
            const uint32_t nb = (uint32_t)((kt + 1) & 1) * FLASH_BUFB;
            const __half* kbt = kb + (size_t)((kt + 1) * 64) * CQKV;
            const __half* vbt = vb + (size_t)((kt + 1) * 64) * CQKV;
            cp16(sb + nb + srow * 144 + sdc * 16, kbt + (size_t)srow * CQKV + sdc * 8);
            cp16(sb + nb + (srow + 32) * 144 + sdc * 16, kbt + (size_t)(srow + 32) * CQKV + sdc * 8);
            cp16(sb + nb + 9216 + srow * 144 + sdc * 16, vbt + (size_t)srow * CQKV + sdc * 8);
            cp16(sb + nb + 9216 + (srow + 32) * 144 + sdc * 16, vbt + (size_t)(srow + 32) * CQKV + sdc * 8);
            CP_COMMIT();
        }

        // ---- S = Q @ K^T ----
        float s[8][4];
#pragma unroll
        for (int nt = 0; nt < 8; ++nt)
#pragma unroll
            for (int v = 0; v < 4; ++v) s[nt][v] = 0.f;

#pragma unroll
        for (int kk = 0; kk < 4; ++kk) {
#pragma unroll
            for (int ntp = 0; ntp < 4; ++ntp) {
                uint32_t b0, b1, b2, b3;
                ldsm4(b0, b1, b2, b3, k_base + bufo + ntp * 2304 + kk * 32);
                mma16(s[2 * ntp],     qa[kk][0], qa[kk][1], qa[kk][2], qa[kk][3], b0, b2);
                mma16(s[2 * ntp + 1], qa[kk][0], qa[kk][1], qa[kk][2], qa[kk][3], b1, b3);
            }
        }

        // scale
#pragma unroll
        for (int nt = 0; nt < 8; ++nt) {
            s[nt][0] *= scale; s[nt][1] *= scale;
            s[nt][2] *= scale; s[nt][3] *= scale;
        }

        // ---- causal mask (near-diagonal tiles only) ----
        if (kt >= 2 * qt) {
            const int cb = kt * 64 + 2 * q;
#pragma unroll
            for (int nt = 0; nt < 8; ++nt) {
                const int c = cb + nt * 8;
                if (c     > row_g0)     s[nt][0] = -1e30f;
                if (c + 1 > row_g0)     s[nt][1] = -1e30f;
                if (c     > row_g0 + 8) s[nt][2] = -1e30f;
                if (c + 1 > row_g0 + 8) s[nt][3] = -1e30f;
            }
        }

        // ---- online softmax ----
        float mx0 = -1e30f, mx1 = -1e30f;
#pragma unroll
        for (int nt = 0; nt < 8; ++nt) {
            mx0 = fmaxf(mx0, fmaxf(s[nt][0], s[nt][1]));
            mx1 = fmaxf(mx1, fmaxf(s[nt][2], s[nt][3]));
        }
        mx0 = fmaxf(mx0, __shfl_xor_sync(0xffffffffu, mx0, 1));
        mx0 = fmaxf(mx0, __shfl_xor_sync(0xffffffffu, mx0, 2));
        mx1 = fmaxf(mx1, __shfl_xor_sync(0xffffffffu, mx1, 1));
        mx1 = fmaxf(mx1, __shfl_xor_sync(0xffffffffu, mx1, 2));

        const float mn0 = fmaxf(m0, mx0);
        const float mn1 = fmaxf(m1, mx1);
        float sum0 = 0.f, sum1 = 0.f;
#pragma unroll
        for (int nt = 0; nt < 8; ++nt) {
            s[nt][0] = __expf(s[nt][0] - mn0);
            s[nt][1] = __expf(s[nt][1] - mn0);
            s[nt][2] = __expf(s[nt][2] - mn1);
            s[nt][3] = __expf(s[nt][3] - mn1);
            sum0 += s[nt][0] + s[nt][1];
            sum1 += s[nt][2] + s[nt][3];
        }
        sum0 += __shfl_xor_sync(0xffffffffu, sum0, 1);
        sum0 += __shfl_xor_sync(0xffffffffu, sum0, 2);
        sum1 += __shfl_xor_sync(0xffffffffu, sum1, 1);
        sum1 += __shfl_xor_sync(0xffffffffu, sum1, 2);

        const float al0 = __expf(m0 - mn0);
        const float al1 = __expf(m1 - mn1);
        m0 = mn0; m1 = mn1;
        l0 = l0 * al0 + sum0;
        l1 = l1 * al1 + sum1;
#pragma unroll
        for (int t = 0; t < 8; ++t) {
            o[t][0] *= al0; o[t][1] *= al0;
            o[t][2] *= al1; o[t][3] *= al1;
        }

        // ---- O += P @ V (V frags via ldmatrix.trans) ----
#pragma unroll
        for (int kk = 0; kk < 4; ++kk) {
            const uint32_t a0 = packh2(s[2 * kk][0],     s[2 * kk][1]);
            const uint32_t a1 = packh2(s[2 * kk][2],     s[2 * kk][3]);
            const uint32_t a2 = packh2(s[2 * kk + 1][0], s[2 * kk + 1][1]);
            const uint32_t a3 = packh2(s[2 * kk + 1][2], s[2 * kk + 1][3]);
#pragma unroll
            for (int dtp = 0; dtp < 4; ++dtp) {
                uint32_t b0, b1, b2, b3;
                ldsm4t(b0, b1, b2, b3, v_base + bufo + kk * 2304 + dtp * 32);
                mma16(o[2 * dtp],     a0, a1, a2, a3, b0, b1);
                mma16(o[2 * dtp + 1], a0, a1, a2, a3, b2, b3);
            }
        }

        if (kt < ktmax) CP_WAIT0();
        __syncthreads();
    }

    // ---- epilogue ----
    {
        const float il0 = 1.f / l0;
        const float il1 = 1.f / l1;
        __half* ob = outh + ((size_t)b * NN + (size_t)qt * 128 + warp * 16 + r0) * DD + h * HDIM;
#pragma unroll
        for (int dt = 0; dt < 8; ++dt) {
            *(uint32_t*)(ob + dt * 8 + 2 * q) =
                packh2(o[dt][0] * il0, o[dt][1] * il0);
            *(uint32_t*)(ob + (size_t)8 * DD + dt * 8 + 2 * q) =
                packh2(o[dt][2] * il1, o[dt][3] * il1);
        }
    }
}

// ---------------------------------------------------------------------------
extern "C" void kernel_launch(void* const* d_in, const int* in_sizes, int n_in,
                              void* d_out, int out_size)
{
    (void)in_sizes; (void)n_in; (void)out_size;
    const float* x    = (const float*)d_in[0];
    const float* Wqkv = (const float*)d_in[1];
    const float* bqkv = (const float*)d_in[2];
    const float* Wout = (const float*)d_in[3];
    const float* bout = (const float*)d_in[4];
    float* out = (float*)d_out;

    __half *qkv, *attn, *xh, *wqkvh, *wouth;
    cudaGetSymbolAddress((void**)&qkv, g_qkv);
    cudaGetSymbolAddress((void**)&attn, g_attn);
    cudaGetSymbolAddress((void**)&xh, g_xh);
    cudaGetSymbolAddress((void**)&wqkvh, g_wqkvh);
    cudaGetSymbolAddress((void**)&wouth, g_wouth);

    static int set_attr = 0;
    if (!set_attr) {
        cudaFuncSetAttribute(gemm_h<true>,  cudaFuncAttributeMaxDynamicSharedMemorySize, GEMM_SMEM);
        cudaFuncSetAttribute(gemm_h<false>, cudaFuncAttributeMaxDynamicSharedMemorySize, GEMM_SMEM);
        cudaFuncSetAttribute(flash_h, cudaFuncAttributeMaxDynamicSharedMemorySize, FLASH_SMEM);
        set_attr = 1;
    }

    // 0) fp32 -> fp16 conversions
    f2h_kernel<<<(BB * NN * DD / 4 + 255) / 256, 256>>>((const float4*)x, (uint2*)xh, BB * NN * DD / 4);
    f2h_kernel<<<(DD * CQKV / 4 + 255) / 256, 256>>>((const float4*)Wqkv, (uint2*)wqkvh, DD * CQKV / 4);
    f2h_kernel<<<(DD * DD / 4 + 255) / 256, 256>>>((const float4*)Wout, (uint2*)wouth, DD * DD / 4);

    // 1) QKV projection
    {
        dim3 grid(CQKV / 128, (BB * NN) / 128);
        gemm_h<true><<<grid, 256, GEMM_SMEM>>>(xh, wqkvh, bqkv, qkv, BB * NN, CQKV, DD);
    }

    // 2) causal flash attention
    flash_h<<<512, 256, FLASH_SMEM>>>(qkv, attn);

    // 3) output projection (fp32 out)
    {
        dim3 grid(DD / 128, (BB * NN) / 128);
        gemm_h<false><<<grid, 256, GEMM_SMEM>>>(attn, wouth, bout, out, BB * NN, DD, DD);
    }
}

// round 7
// speedup vs baseline: 7.5943x; 1.0480x over previous
#include <cuda_runtime.h>
#include <cuda_fp16.h>
#include <stdint.h>

#define BB   2
#define NN   4096
#define DD   512
#define HH   8
#define HDIM 64
#define CQKV 1536

// Scratch (static device arrays — no runtime allocation)
__device__ __half g_qkv[(size_t)BB * NN * CQKV];    // [B,N,3,H,HD]
__device__ __half g_attn[(size_t)BB * NN * DD];     // [B,N,D]
__device__ __half g_xh[(size_t)BB * NN * DD];       // fp16 copy of x
__device__ __half g_wqkvh[(size_t)DD * CQKV];       // fp16 copy of W_qkv
__device__ __half g_wouth[(size_t)DD * DD];         // fp16 copy of W_out

// ---------------------------------------------------------------------------
// helpers
// ---------------------------------------------------------------------------
__device__ __forceinline__ uint32_t packh2(float lo, float hi) {
    __half2 h = __floats2half2_rn(lo, hi);
    return *(uint32_t*)&h;
}

__device__ __forceinline__ void mma16(float* c,
    uint32_t a0, uint32_t a1, uint32_t a2, uint32_t a3,
    uint32_t b0, uint32_t b1)
{
    asm volatile(
        "mma.sync.aligned.m16n8k16.row.col.f32.f16.f16.f32 "
        "{%0,%1,%2,%3}, {%4,%5,%6,%7}, {%8,%9}, {%0,%1,%2,%3};"
        : "+f"(c[0]), "+f"(c[1]), "+f"(c[2]), "+f"(c[3])
        : "r"(a0), "r"(a1), "r"(a2), "r"(a3), "r"(b0), "r"(b1));
}

__device__ __forceinline__ void cp16(uint32_t dst, const void* src) {
    asm volatile("cp.async.cg.shared.global [%0], [%1], 16;"
                 :: "r"(dst), "l"(src));
}
#define CP_COMMIT() asm volatile("cp.async.commit_group;")
#define CP_WAIT1()  asm volatile("cp.async.wait_group 1;")
#define CP_WAIT2()  asm volatile("cp.async.wait_group 2;")

__device__ __forceinline__ void ldsm4(uint32_t& r0, uint32_t& r1,
                                      uint32_t& r2, uint32_t& r3, uint32_t a) {
    asm volatile("ldmatrix.sync.aligned.m8n8.x4.shared.b16 {%0,%1,%2,%3}, [%4];"
        : "=r"(r0), "=r"(r1), "=r"(r2), "=r"(r3) : "r"(a));
}
__device__ __forceinline__ void ldsm4t(uint32_t& r0, uint32_t& r1,
                                       uint32_t& r2, uint32_t& r3, uint32_t a) {
    asm volatile("ldmatrix.sync.aligned.m8n8.x4.trans.shared.b16 {%0,%1,%2,%3}, [%4];"
        : "=r"(r0), "=r"(r1), "=r"(r2), "=r"(r3) : "r"(a));
}

// ---------------------------------------------------------------------------
// fp32 -> fp16 conversion (one-time)
// ---------------------------------------------------------------------------
__global__ __launch_bounds__(256) void f2h_kernel(
    const float4* __restrict__ src, uint2* __restrict__ dst, int n4)
{
    const int i = blockIdx.x * 256 + threadIdx.x;
    if (i < n4) {
        float4 v = src[i];
        dst[i] = make_uint2(packh2(v.x, v.y), packh2(v.z, v.w));
    }
}

// ---------------------------------------------------------------------------
// fp16 GEMM: C = A[M,K] @ W[K,N] + bias. 4-stage cp.async pipeline.
// BM=128, BN=128, BK=32, 256 thr (8 warps 2x4), warp tile 64x32.
// Per-stage smem: A 128x80=10240 B, B 32x272=8704 B -> 18944 B; 4 stages.
// ---------------------------------------------------------------------------
#define GEMM_BUFB 18944
#define GEMM_SMEM (4 * GEMM_BUFB)

template<bool C_HALF>
__global__ __launch_bounds__(256, 2) void gemm_h(
    const __half* __restrict__ A, const __half* __restrict__ W,
    const float* __restrict__ bias, void* __restrict__ Cp,
    int M, int Nc, int K)
{
    extern __shared__ char gsm[];
    const uint32_t sb = (uint32_t)__cvta_generic_to_shared(gsm);

    const int tid  = threadIdx.x;
    const int lane = tid & 31;
    const int warp = tid >> 5;
    const int wm = warp >> 2;
    const int wn = warp & 3;
    const int r0 = lane >> 2;
    const int q  = lane & 3;
    const int row0 = blockIdx.y * 128;
    const int col0 = blockIdx.x * 128;

    // cp.async staging geometry
    const int arow = tid >> 2;        // 0..63 (+64)
    const int adc  = tid & 3;         // 16B chunk in k
    const int brow = tid >> 4;        // 0..15 (+16)
    const int bnc  = tid & 15;        // 16B chunk in n

    const __half* Ag = A + (size_t)(row0 + arow) * K + adc * 8;
    const __half* Wg = W + (size_t)brow * Nc + col0 + bnc * 8;

    // fragment base addresses
    const uint32_t a_base = sb + (wm * 64 + (lane & 15)) * 80 + (lane >> 4) * 16;
    const uint32_t b_base = sb + 10240 +
        ((lane & 7) + ((lane >> 3) & 1) * 8) * 272 + wn * 64 + (lane >> 4) * 16;

    float acc[4][4][4];
#pragma unroll
    for (int i = 0; i < 4; ++i)
#pragma unroll
        for (int j = 0; j < 4; ++j)
#pragma unroll
            for (int v = 0; v < 4; ++v) acc[i][j][v] = 0.f;

    const int nk = K >> 5;

    // prologue: stage slabs 0,1,2 (one commit group each)
#pragma unroll
    for (int s = 0; s < 3; ++s) {
        const uint32_t nb = (uint32_t)s * GEMM_BUFB;
        const int k0 = s * 32;
        cp16(sb + nb + arow * 80 + adc * 16, Ag + k0);
        cp16(sb + nb + (arow + 64) * 80 + adc * 16, Ag + (size_t)64 * K + k0);
        cp16(sb + nb + 10240 + brow * 272 + bnc * 16, Wg + (size_t)k0 * Nc);
        cp16(sb + nb + 10240 + (brow + 16) * 272 + bnc * 16,
             Wg + (size_t)(k0 + 16) * Nc);
        CP_COMMIT();
    }
    CP_WAIT2();          // slab 0 complete
    __syncthreads();

    for (int it = 0; it < nk; ++it) {
        const uint32_t bufo = (uint32_t)(it & 3) * GEMM_BUFB;

        // stage slab it+3 (empty commit keeps group accounting uniform)
        if (it + 3 < nk) {
            const int k0 = (it + 3) * 32;
            const uint32_t nb = (uint32_t)((it + 3) & 3) * GEMM_BUFB;
            cp16(sb + nb + arow * 80 + adc * 16, Ag + k0);
            cp16(sb + nb + (arow + 64) * 80 + adc * 16, Ag + (size_t)64 * K + k0);
            cp16(sb + nb + 10240 + brow * 272 + bnc * 16, Wg + (size_t)k0 * Nc);
            cp16(sb + nb + 10240 + (brow + 16) * 272 + bnc * 16,
                 Wg + (size_t)(k0 + 16) * Nc);
        }
        CP_COMMIT();

#pragma unroll
        for (int kk = 0; kk < 2; ++kk) {
            uint32_t a[4][4];
#pragma unroll
            for (int mt = 0; mt < 4; ++mt)
                ldsm4(a[mt][0], a[mt][1], a[mt][2], a[mt][3],
                      a_base + bufo + mt * 1280 + kk * 32);
#pragma unroll
            for (int ntp = 0; ntp < 2; ++ntp) {
                uint32_t b0, b1, b2, b3;
                ldsm4t(b0, b1, b2, b3, b_base + bufo + kk * 4352 + ntp * 32);
#pragma unroll
                for (int mt = 0; mt < 4; ++mt) {
                    mma16(acc[mt][2 * ntp],     a[mt][0], a[mt][1], a[mt][2], a[mt][3], b0, b1);
                    mma16(acc[mt][2 * ntp + 1], a[mt][0], a[mt][1], a[mt][2], a[mt][3], b2, b3);
                }
            }
        }

        CP_WAIT2();      // slab it+1 guaranteed complete
        __syncthreads();
    }

    // epilogue: bias + store
#pragma unroll
    for (int mt = 0; mt < 4; ++mt) {
        const int r = row0 + wm * 64 + mt * 16 + r0;
#pragma unroll
        for (int nt = 0; nt < 4; ++nt) {
            const int c = col0 + wn * 32 + nt * 8 + 2 * q;
            const float bx = bias[c], by = bias[c + 1];
            if (C_HALF) {
                __half* Ch = (__half*)Cp;
                *(uint32_t*)(Ch + (size_t)r * Nc + c)       = packh2(acc[mt][nt][0] + bx, acc[mt][nt][1] + by);
                *(uint32_t*)(Ch + (size_t)(r + 8) * Nc + c) = packh2(acc[mt][nt][2] + bx, acc[mt][nt][3] + by);
            } else {
                float* Cf = (float*)Cp;
                float2 v0 = { acc[mt][nt][0] + bx, acc[mt][nt][1] + by };
                float2 v1 = { acc[mt][nt][2] + bx, acc[mt][nt][3] + by };
                *(float2*)&Cf[(size_t)r * Nc + c] = v0;
                *(float2*)&Cf[(size_t)(r + 8) * Nc + c] = v1;
            }
        }
    }
}

// ---------------------------------------------------------------------------
// Flash attention fp16: BM=128 (8 warps), BN=64. 3-stage cp.async K/V
// pipeline + dedicated Q region (full 128x144 B = 18432 B!); ldmatrix frags
// (V via .trans); exp2-domain online softmax.
// smem: 3 x 18432 (K/V stages) + 18432 (Q) = 73728 B. 2 CTAs/SM.
// ---------------------------------------------------------------------------
#define FLASH_BUFB 18432
#define FLASH_QOFF (3 * FLASH_BUFB)
#define FLASH_SMEM (FLASH_QOFF + 18432)

__global__ __launch_bounds__(256, 2) void flash_h(
    const __half* __restrict__ qkv, __half* __restrict__ outh)
{
    extern __shared__ char fss[];
    const uint32_t sb = (uint32_t)__cvta_generic_to_shared(fss);

    const int tid  = threadIdx.x;
    const int lane = tid & 31;
    const int warp = tid >> 5;
    const int r0 = lane >> 2;
    const int q  = lane & 3;

    const int idx = blockIdx.x;          // heavy qt first
    const int qt  = 31 - (idx >> 4);
    const int h   = idx & 7;
    const int b   = (idx >> 3) & 1;
    const float cexp = 0.125f * 1.44269504089f;   // scale * log2(e)

    const int srow = tid >> 3;           // 0..31 (+32)
    const int sdc  = tid & 7;            // 16B chunk in d

    const __half* qb = qkv + ((size_t)b * NN + (size_t)qt * 128) * CQKV + h * HDIM;
    const __half* kb = qkv + (size_t)b * NN * CQKV + DD + h * HDIM;
    const __half* vb = qkv + (size_t)b * NN * CQKV + 2 * DD + h * HDIM;

    const int ktmax = 2 * qt + 1;

    // ---- prologue: group0 = Q + K0/V0; group1 = K1/V1 ----
    {
#pragma unroll
        for (int i = 0; i < 4; ++i) {
            const int c = tid + 256 * i;
            const int row = c >> 3, dc = c & 7;
            cp16(sb + FLASH_QOFF + row * 144 + dc * 16, qb + (size_t)row * CQKV + dc * 8);
        }
        cp16(sb + srow * 144 + sdc * 16, kb + (size_t)srow * CQKV + sdc * 8);
        cp16(sb + (srow + 32) * 144 + sdc * 16, kb + (size_t)(srow + 32) * CQKV + sdc * 8);
        cp16(sb + 9216 + srow * 144 + sdc * 16, vb + (size_t)srow * CQKV + sdc * 8);
        cp16(sb + 9216 + (srow + 32) * 144 + sdc * 16, vb + (size_t)(srow + 32) * CQKV + sdc * 8);
        CP_COMMIT();

        const __half* kbt = kb + (size_t)64 * CQKV;
        const __half* vbt = vb + (size_t)64 * CQKV;
        const uint32_t nb = FLASH_BUFB;
        cp16(sb + nb + srow * 144 + sdc * 16, kbt + (size_t)srow * CQKV + sdc * 8);
        cp16(sb + nb + (srow + 32) * 144 + sdc * 16, kbt + (size_t)(srow + 32) * CQKV + sdc * 8);
        cp16(sb + nb + 9216 + srow * 144 + sdc * 16, vbt + (size_t)srow * CQKV + sdc * 8);
        cp16(sb + nb + 9216 + (srow + 32) * 144 + sdc * 16, vbt + (size_t)(srow + 32) * CQKV + sdc * 8);
        CP_COMMIT();
    }
    CP_WAIT1();          // group0 (Q + slab0) complete
    __syncthreads();

    // ---- preload Q A-fragments ----
    uint32_t qa[4][4];
    {
        const uint32_t q_base = sb + FLASH_QOFF +
            (warp * 16 + (lane & 15)) * 144 + (lane >> 4) * 16;
#pragma unroll
        for (int kk = 0; kk < 4; ++kk)
            ldsm4(qa[kk][0], qa[kk][1], qa[kk][2], qa[kk][3], q_base + kk * 32);
    }

    // fragment bases
    const uint32_t k_base = sb + ((lane & 7) + ((lane >> 3) & 1) * 8) * 144 + (lane >> 4) * 16;
    const uint32_t v_base = k_base + 9216;

    float o[8][4];
#pragma unroll
    for (int t = 0; t < 8; ++t)
#pragma unroll
        for (int v = 0; v < 4; ++v) o[t][v] = 0.f;
    float m0 = -1e30f, m1 = -1e30f, l0 = 0.f, l1 = 0.f;

    const int row_g0 = qt * 128 + warp * 16 + r0;

    int buf = 0;
    for (int kt = 0; kt <= ktmax; ++kt) {
        const uint32_t bufo = (uint32_t)buf * FLASH_BUFB;
        buf = (buf == 2) ? 0 : buf + 1;

        // stage slab kt+2 (empty commit when out of range keeps accounting uniform)
        if (kt + 2 <= ktmax) {
            const int s = (kt + 2) % 3;
            const uint32_t nb = (uint32_t)s * FLASH_BUFB;
            const __half* kbt = kb + (size_t)((kt + 2) * 64) * CQKV;
            const __half* vbt = vb + (size_t)((kt + 2) * 64) * CQKV;
            cp16(sb + nb + srow * 144 + sdc * 16, kbt + (size_t)srow * CQKV + sdc * 8);
            cp16(sb + nb + (srow + 32) * 144 + sdc * 16, kbt + (size_t)(srow + 32) * CQKV + sdc * 8);
            cp16(sb + nb + 9216 + srow * 144 + sdc * 16, vbt + (size_t)srow * CQKV + sdc * 8);
            cp16(sb + nb + 9216 + (srow + 32) * 144 + sdc * 16, vbt + (size_t)(srow + 32) * CQKV + sdc * 8);
        }
        CP_COMMIT();

        // ---- S = Q @ K^T ----
        float s[8][4];
#pragma unroll
        for (int nt = 0; nt < 8; ++nt)
#pragma unroll
            for (int v = 0; v < 4; ++v) s[nt][v] = 0.f;

#pragma unroll
        for (int kk = 0; kk < 4; ++kk) {
#pragma unroll
            for (int ntp = 0; ntp < 4; ++ntp) {
                uint32_t b0, b1, b2, b3;
                ldsm4(b0, b1, b2, b3, k_base + bufo + ntp * 2304 + kk * 32);
                mma16(s[2 * ntp],     qa[kk][0], qa[kk][1], qa[kk][2], qa[kk][3], b0, b2);
                mma16(s[2 * ntp + 1], qa[kk][0], qa[kk][1], qa[kk][2], qa[kk][3], b1, b3);
            }
        }

        // convert to log2-domain (scale * log2e folded)
#pragma unroll
        for (int nt = 0; nt < 8; ++nt) {
            s[nt][0] *= cexp; s[nt][1] *= cexp;
            s[nt][2] *= cexp; s[nt][3] *= cexp;
        }

        // ---- causal mask (near-diagonal tiles only) ----
        if (kt >= 2 * qt) {
            const int cb = kt * 64 + 2 * q;
#pragma unroll
            for (int nt = 0; nt < 8; ++nt) {
                const int c = cb + nt * 8;
                if (c     > row_g0)     s[nt][0] = -1e30f;
                if (c + 1 > row_g0)     s[nt][1] = -1e30f;
                if (c     > row_g0 + 8) s[nt][2] = -1e30f;
                if (c + 1 > row_g0 + 8) s[nt][3] = -1e30f;
            }
        }

        // ---- online softmax (exp2 domain) ----
        float mx0 = -1e30f, mx1 = -1e30f;
#pragma unroll
        for (int nt = 0; nt < 8; ++nt) {
            mx0 = fmaxf(mx0, fmaxf(s[nt][0], s[nt][1]));
            mx1 = fmaxf(mx1, fmaxf(s[nt][2], s[nt][3]));
        }
        mx0 = fmaxf(mx0, __shfl_xor_sync(0xffffffffu, mx0, 1));
        mx0 = fmaxf(mx0, __shfl_xor_sync(0xffffffffu, mx0, 2));
        mx1 = fmaxf(mx1, __shfl_xor_sync(0xffffffffu, mx1, 1));
        mx1 = fmaxf(mx1, __shfl_xor_sync(0xffffffffu, mx1, 2));

        const float mn0 = fmaxf(m0, mx0);
        const float mn1 = fmaxf(m1, mx1);
        float sum0 = 0.f, sum1 = 0.f;
#pragma unroll
        for (int nt = 0; nt < 8; ++nt) {
            s[nt][0] = exp2f(s[nt][0] - mn0);
            s[nt][1] = exp2f(s[nt][1] - mn0);
            s[nt][2] = exp2f(s[nt][2] - mn1);
            s[nt][3] = exp2f(s[nt][3] - mn1);
            sum0 += s[nt][0] + s[nt][1];
            sum1 += s[nt][2] + s[nt][3];
        }
        sum0 += __shfl_xor_sync(0xffffffffu, sum0, 1);
        sum0 += __shfl_xor_sync(0xffffffffu, sum0, 2);
        sum1 += __shfl_xor_sync(0xffffffffu, sum1, 1);
        sum1 += __shfl_xor_sync(0xffffffffu, sum1, 2);

        const float al0 = exp2f(m0 - mn0);
        const float al1 = exp2f(m1 - mn1);
        m0 = mn0; m1 = mn1;
        l0 = l0 * al0 + sum0;
        l1 = l1 * al1 + sum1;
#pragma unroll
        for (int t = 0; t < 8; ++t) {
            o[t][0] *= al0; o[t][1] *= al0;
            o[t][2] *= al1; o[t][3] *= al1;
        }

        // ---- O += P @ V (V frags via ldmatrix.trans) ----
#pragma unroll
        for (int kk = 0; kk < 4; ++kk) {
            const uint32_t a0 = packh2(s[2 * kk][0],     s[2 * kk][1]);
            const uint32_t a1 = packh2(s[2 * kk][2],     s[2 * kk][3]);
            const uint32_t a2 = packh2(s[2 * kk + 1][0], s[2 * kk + 1][1]);
            const uint32_t a3 = packh2(s[2 * kk + 1][2], s[2 * kk + 1][3]);
#pragma unroll
            for (int dtp = 0; dtp < 4; ++dtp) {
                uint32_t b0, b1, b2, b3;
                ldsm4t(b0, b1, b2, b3, v_base + bufo + kk * 2304 + dtp * 32);
                mma16(o[2 * dtp],     a0, a1, a2, a3, b0, b1);
                mma16(o[2 * dtp + 1], a0, a1, a2, a3, b2, b3);
            }
        }

        CP_WAIT1();      // slab kt+1 complete
        __syncthreads();
    }

    // ---- epilogue ----
    {
        const float il0 = 1.f / l0;
        const float il1 = 1.f / l1;
        __half* ob = outh + ((size_t)b * NN + (size_t)qt * 128 + warp * 16 + r0) * DD + h * HDIM;
#pragma unroll
        for (int dt = 0; dt < 8; ++dt) {
            *(uint32_t*)(ob + dt * 8 + 2 * q) =
                packh2(o[dt][0] * il0, o[dt][1] * il0);
            *(uint32_t*)(ob + (size_t)8 * DD + dt * 8 + 2 * q) =
                packh2(o[dt][2] * il1, o[dt][3] * il1);
        }
    }
}

// ---------------------------------------------------------------------------
extern "C" void kernel_launch(void* const* d_in, const int* in_sizes, int n_in,
                              void* d_out, int out_size)
{
    (void)in_sizes; (void)n_in; (void)out_size;
    const float* x    = (const float*)d_in[0];
    const float* Wqkv = (const float*)d_in[1];
    const float* bqkv = (const float*)d_in[2];
    const float* Wout = (const float*)d_in[3];
    const float* bout = (const float*)d_in[4];
    float* out = (float*)d_out;

    __half *qkv, *attn, *xh, *wqkvh, *wouth;
    cudaGetSymbolAddress((void**)&qkv, g_qkv);
    cudaGetSymbolAddress((void**)&attn, g_attn);
    cudaGetSymbolAddress((void**)&xh, g_xh);
    cudaGetSymbolAddress((void**)&wqkvh, g_wqkvh);
    cudaGetSymbolAddress((void**)&wouth, g_wouth);

    static int set_attr = 0;
    if (!set_attr) {
        cudaFuncSetAttribute(gemm_h<true>,  cudaFuncAttributeMaxDynamicSharedMemorySize, GEMM_SMEM);
        cudaFuncSetAttribute(gemm_h<false>, cudaFuncAttributeMaxDynamicSharedMemorySize, GEMM_SMEM);
        cudaFuncSetAttribute(flash_h, cudaFuncAttributeMaxDynamicSharedMemorySize, FLASH_SMEM);
        set_attr = 1;
    }

    // 0) fp32 -> fp16 conversions
    f2h_kernel<<<(BB * NN * DD / 4 + 255) / 256, 256>>>((const float4*)x, (uint2*)xh, BB * NN * DD / 4);
    f2h_kernel<<<(DD * CQKV / 4 + 255) / 256, 256>>>((const float4*)Wqkv, (uint2*)wqkvh, DD * CQKV / 4);
    f2h_kernel<<<(DD * DD / 4 + 255) / 256, 256>>>((const float4*)Wout, (uint2*)wouth, DD * DD / 4);

    // 1) QKV projection
    {
        dim3 grid(CQKV / 128, (BB * NN) / 128);
        gemm_h<true><<<grid, 256, GEMM_SMEM>>>(xh, wqkvh, bqkv, qkv, BB * NN, CQKV, DD);
    }

    // 2) causal flash attention
    flash_h<<<512, 256, FLASH_SMEM>>>(qkv, attn);

    // 3) output projection (fp32 out)
    {
        dim3 grid(DD / 128, (BB * NN) / 128);
        gemm_h<false><<<grid, 256, GEMM_SMEM>>>(attn, wouth, bout, out, BB * NN, DD, DD);
    }
}